// round 2
// baseline (speedup 1.0000x reference)
#include <cuda_runtime.h>
#include <cuda_bf16.h>
#include <math.h>

// Problem constants
#define LNUM 2
#define HNUM 16
#define DMODEL 1024
#define FF 4096
#define BATCH 2
#define SEQ 2048
#define DKH 64
#define LN_EPS 1e-5f

#define ROWS (BATCH * SEQ)          // 4096
#define BH (BATCH * HNUM)           // 32

// ---------------- device scratch (static globals; no allocs allowed) ----------------
__device__ float g_h   [(size_t)ROWS * DMODEL];   // layernorm output
__device__ float g_q   [(size_t)ROWS * DMODEL];
__device__ float g_k   [(size_t)ROWS * DMODEL];
__device__ float g_v   [(size_t)ROWS * DMODEL];
__device__ float g_ao  [(size_t)ROWS * DMODEL];   // attention output (pre O-proj), [B,S,H,DK]
__device__ float g_ff  [(size_t)ROWS * FF];       // FFN intermediate
__device__ float g_buf0[(size_t)ROWS * DMODEL];   // residual ping
__device__ float g_buf1[(size_t)ROWS * DMODEL];   // residual pong
__device__ float g_scores[(size_t)BH * SEQ * SEQ];// 1 GiB attention scores

// ---------------- LayerNorm: one block per row, D=1024, 256 threads ----------------
__global__ void __launch_bounds__(256)
ln_kernel(const float* __restrict__ in, const float* __restrict__ gamma,
          const float* __restrict__ beta, float* __restrict__ out)
{
    const int row = blockIdx.x;
    const float* x = in + (size_t)row * DMODEL;
    float* o = out + (size_t)row * DMODEL;
    const int tid = threadIdx.x;

    float v[4];
    float s = 0.f, ss = 0.f;
#pragma unroll
    for (int j = 0; j < 4; j++) {
        v[j] = x[tid + j * 256];
        s += v[j];
        ss += v[j] * v[j];
    }
    // warp reduce
#pragma unroll
    for (int o2 = 16; o2 > 0; o2 >>= 1) {
        s  += __shfl_xor_sync(0xffffffffu, s,  o2);
        ss += __shfl_xor_sync(0xffffffffu, ss, o2);
    }
    __shared__ float red[18];
    const int warp = tid >> 5, lane = tid & 31;
    if (lane == 0) { red[warp] = s; red[warp + 8] = ss; }
    __syncthreads();
    if (tid == 0) {
        float ts = 0.f, tss = 0.f;
#pragma unroll
        for (int w = 0; w < 8; w++) { ts += red[w]; tss += red[w + 8]; }
        float mu = ts / (float)DMODEL;
        float var = tss / (float)DMODEL - mu * mu;
        red[16] = mu;
        red[17] = rsqrtf(var + LN_EPS);
    }
    __syncthreads();
    const float mu = red[16], rstd = red[17];
#pragma unroll
    for (int j = 0; j < 4; j++) {
        int idx = tid + j * 256;
        o[idx] = (v[j] - mu) * rstd * gamma[idx] + beta[idx];
    }
}

// ---------------- Row softmax over length SEQ (2048), one block per row ----------------
__global__ void __launch_bounds__(256)
softmax_kernel(float* __restrict__ p)
{
    const size_t row = blockIdx.x;
    float* x = p + row * (size_t)SEQ;
    const int tid = threadIdx.x;

    float v[8];
    float m = -INFINITY;
#pragma unroll
    for (int j = 0; j < 8; j++) {
        v[j] = x[tid + j * 256];
        m = fmaxf(m, v[j]);
    }
#pragma unroll
    for (int o2 = 16; o2 > 0; o2 >>= 1)
        m = fmaxf(m, __shfl_xor_sync(0xffffffffu, m, o2));
    __shared__ float red[10];
    const int warp = tid >> 5, lane = tid & 31;
    if (lane == 0) red[warp] = m;
    __syncthreads();
    if (tid == 0) {
        float tm = red[0];
#pragma unroll
        for (int w = 1; w < 8; w++) tm = fmaxf(tm, red[w]);
        red[8] = tm;
    }
    __syncthreads();
    m = red[8];

    float sum = 0.f;
#pragma unroll
    for (int j = 0; j < 8; j++) {
        v[j] = __expf(v[j] - m);
        sum += v[j];
    }
#pragma unroll
    for (int o2 = 16; o2 > 0; o2 >>= 1)
        sum += __shfl_xor_sync(0xffffffffu, sum, o2);
    if (lane == 0) red[warp] = sum;
    __syncthreads();
    if (tid == 0) {
        float ts = 0.f;
#pragma unroll
        for (int w = 0; w < 8; w++) ts += red[w];
        red[9] = 1.f / ts;
    }
    __syncthreads();
    const float inv = red[9];
#pragma unroll
    for (int j = 0; j < 8; j++)
        x[tid + j * 256] = v[j] * inv;
}

// ---------------- Generic batched tiled SGEMM ----------------
// C[z] = alpha * A[z] (@ or @T) B[z] + bias + res, optional relu.
// Batch offset: z1 = z / zdiv, z2 = z % zdiv; ptr += z1*s1 + z2*s2.
// TB=false: B is [K,N] row-major (ldb). TB=true: B is [N,K] row-major (ldb).
template <bool TB>
__global__ void __launch_bounds__(256)
gemm_kernel(const float* __restrict__ A, int lda, long long sA1, long long sA2,
            const float* __restrict__ B, int ldb, long long sB1, long long sB2,
            const float* __restrict__ bias,
            const float* __restrict__ res,
            float* __restrict__ C, int ldc, long long sC1, long long sC2,
            int M, int N, int K, int zdiv, float alpha, int relu)
{
    const int z = blockIdx.z;
    const long long z1 = z / zdiv, z2 = z % zdiv;
    A += z1 * sA1 + z2 * sA2;
    B += z1 * sB1 + z2 * sB2;
    C += z1 * sC1 + z2 * sC2;
    if (res) res += z1 * sC1 + z2 * sC2;

    __shared__ float As[16][64];
    __shared__ float Bs[16][64];

    const int bm = blockIdx.y * 64, bn = blockIdx.x * 64;
    const int tid = threadIdx.x;
    const int tx = tid & 15, ty = tid >> 4;

    float acc[4][4] = {};

    for (int k0 = 0; k0 < K; k0 += 16) {
        // load A tile [64 x 16] transposed into As[k][m]
#pragma unroll
        for (int j = 0; j < 4; j++) {
            int idx = tid + j * 256;
            int r = idx >> 4, c = idx & 15;
            int gr = bm + r, gc = k0 + c;
            As[c][r] = (gr < M && gc < K) ? A[(long long)gr * lda + gc] : 0.f;
        }
        if (!TB) {
#pragma unroll
            for (int j = 0; j < 4; j++) {
                int idx = tid + j * 256;
                int r = idx >> 6, c = idx & 63;
                int gk = k0 + r, gn = bn + c;
                Bs[r][c] = (gk < K && gn < N) ? B[(long long)gk * ldb + gn] : 0.f;
            }
        } else {
#pragma unroll
            for (int j = 0; j < 4; j++) {
                int idx = tid + j * 256;
                int n = idx >> 4, c = idx & 15;
                int gn = bn + n, gk = k0 + c;
                Bs[c][n] = (gn < N && gk < K) ? B[(long long)gn * ldb + gk] : 0.f;
            }
        }
        __syncthreads();

#pragma unroll
        for (int kk = 0; kk < 16; kk++) {
            float a[4], b[4];
#pragma unroll
            for (int i = 0; i < 4; i++) { a[i] = As[kk][ty * 4 + i]; b[i] = Bs[kk][tx * 4 + i]; }
#pragma unroll
            for (int i = 0; i < 4; i++)
#pragma unroll
                for (int j = 0; j < 4; j++)
                    acc[i][j] += a[i] * b[j];
        }
        __syncthreads();
    }

#pragma unroll
    for (int i = 0; i < 4; i++) {
        int row = bm + ty * 4 + i;
        if (row >= M) continue;
#pragma unroll
        for (int j = 0; j < 4; j++) {
            int col = bn + tx * 4 + j;
            if (col >= N) continue;
            float v = acc[i][j] * alpha;
            if (bias) v += bias[col];
            if (res)  v += res[(long long)row * ldc + col];
            if (relu) v = fmaxf(v, 0.f);
            C[(long long)row * ldc + col] = v;
        }
    }
}

// ---------------- host orchestration ----------------
static inline dim3 gemm_grid(int M, int N, int batch)
{
    return dim3((N + 63) / 64, (M + 63) / 64, batch);
}

extern "C" void kernel_launch(void* const* d_in, const int* in_sizes, int n_in,
                              void* d_out, int out_size)
{
    (void)in_sizes; (void)n_in;
    const float* x    = (const float*)d_in[0];
    const float* Wq   = (const float*)d_in[1];
    const float* bq   = (const float*)d_in[2];
    const float* Wk   = (const float*)d_in[3];
    const float* bk   = (const float*)d_in[4];
    const float* Wv   = (const float*)d_in[5];
    const float* bv   = (const float*)d_in[6];
    const float* Wo   = (const float*)d_in[7];
    const float* bo   = (const float*)d_in[8];
    const float* W1   = (const float*)d_in[9];
    const float* b1   = (const float*)d_in[10];
    const float* W2   = (const float*)d_in[11];
    const float* b2   = (const float*)d_in[12];
    const float* gin  = (const float*)d_in[13];
    const float* bin  = (const float*)d_in[14];
    const float* gat  = (const float*)d_in[15];
    const float* bat  = (const float*)d_in[16];
    const float* gou  = (const float*)d_in[17];
    const float* bou  = (const float*)d_in[18];
    float* out = (float*)d_out;
    (void)out_size;

    float *p_h, *p_q, *p_k, *p_v, *p_ao, *p_ff, *p_b0, *p_b1, *p_sc;
    cudaGetSymbolAddress((void**)&p_h,  g_h);
    cudaGetSymbolAddress((void**)&p_q,  g_q);
    cudaGetSymbolAddress((void**)&p_k,  g_k);
    cudaGetSymbolAddress((void**)&p_v,  g_v);
    cudaGetSymbolAddress((void**)&p_ao, g_ao);
    cudaGetSymbolAddress((void**)&p_ff, g_ff);
    cudaGetSymbolAddress((void**)&p_b0, g_buf0);
    cudaGetSymbolAddress((void**)&p_b1, g_buf1);
    cudaGetSymbolAddress((void**)&p_sc, g_scores);

    // out := x
    cudaMemcpyAsync(p_b0, x, (size_t)ROWS * DMODEL * sizeof(float),
                    cudaMemcpyDeviceToDevice);
    float* cur = p_b0;
    float* nxt = p_b1;

    const long long sQ1 = (long long)SEQ * DMODEL;   // per-batch stride in q/k/v/ao
    const long long sQ2 = DKH;                        // per-head offset
    const long long sS1 = (long long)HNUM * SEQ * SEQ;
    const long long sS2 = (long long)SEQ * SEQ;
    const float inv_sqrt_dk = 0.125f;                 // 1/sqrt(64)

    for (int l = 0; l < LNUM; l++) {
        const float* wq = Wq + (size_t)l * DMODEL * DMODEL;
        const float* wk = Wk + (size_t)l * DMODEL * DMODEL;
        const float* wv = Wv + (size_t)l * DMODEL * DMODEL;
        const float* wo = Wo + (size_t)l * DMODEL * DMODEL;
        const float* w1 = W1 + (size_t)l * DMODEL * FF;
        const float* w2 = W2 + (size_t)l * FF * DMODEL;
        const float* vbq = bq + (size_t)l * DMODEL;
        const float* vbk = bk + (size_t)l * DMODEL;
        const float* vbv = bv + (size_t)l * DMODEL;
        const float* vbo = bo + (size_t)l * DMODEL;
        const float* vb1 = b1 + (size_t)l * FF;
        const float* vb2 = b2 + (size_t)l * DMODEL;

        // h = LN(out)
        ln_kernel<<<ROWS, 256>>>(cur, gin, bin, p_h);

        // q/k/v = h @ W + b
        gemm_kernel<false><<<gemm_grid(ROWS, DMODEL, 1), 256>>>(
            p_h, DMODEL, 0, 0, wq, DMODEL, 0, 0, vbq, nullptr,
            p_q, DMODEL, 0, 0, ROWS, DMODEL, DMODEL, 1, 1.f, 0);
        gemm_kernel<false><<<gemm_grid(ROWS, DMODEL, 1), 256>>>(
            p_h, DMODEL, 0, 0, wk, DMODEL, 0, 0, vbk, nullptr,
            p_k, DMODEL, 0, 0, ROWS, DMODEL, DMODEL, 1, 1.f, 0);
        gemm_kernel<false><<<gemm_grid(ROWS, DMODEL, 1), 256>>>(
            p_h, DMODEL, 0, 0, wv, DMODEL, 0, 0, vbv, nullptr,
            p_v, DMODEL, 0, 0, ROWS, DMODEL, DMODEL, 1, 1.f, 0);

        // scores[b,h] = q[b,:,h] @ k[b,:,h]^T * scale   (batched NT, batch=32)
        gemm_kernel<true><<<gemm_grid(SEQ, SEQ, BH), 256>>>(
            p_q, DMODEL, sQ1, sQ2, p_k, DMODEL, sQ1, sQ2, nullptr, nullptr,
            p_sc, SEQ, sS1, sS2, SEQ, SEQ, DKH, HNUM, inv_sqrt_dk, 0);

        // softmax over rows (B*H*S rows of length S)
        softmax_kernel<<<BH * SEQ, 256>>>(p_sc);

        // ao[b,:,h] = P[b,h] @ v[b,:,h]   (batched NN, batch=32, N=64)
        gemm_kernel<false><<<gemm_grid(SEQ, DKH, BH), 256>>>(
            p_sc, SEQ, sS1, sS2, p_v, DMODEL, sQ1, sQ2, nullptr, nullptr,
            p_ao, DMODEL, sQ1, sQ2, SEQ, DKH, SEQ, HNUM, 1.f, 0);

        // out = out + ao @ Wo + bo
        gemm_kernel<false><<<gemm_grid(ROWS, DMODEL, 1), 256>>>(
            p_ao, DMODEL, 0, 0, wo, DMODEL, 0, 0, vbo, cur,
            nxt, DMODEL, 0, 0, ROWS, DMODEL, DMODEL, 1, 1.f, 0);
        { float* t = cur; cur = nxt; nxt = t; }

        // h = LN(out); ff = relu(h@W1+b1)@W2+b2; out = out + ff
        ln_kernel<<<ROWS, 256>>>(cur, gat, bat, p_h);
        gemm_kernel<false><<<gemm_grid(ROWS, FF, 1), 256>>>(
            p_h, DMODEL, 0, 0, w1, FF, 0, 0, vb1, nullptr,
            p_ff, FF, 0, 0, ROWS, FF, DMODEL, 1, 1.f, 1);
        gemm_kernel<false><<<gemm_grid(ROWS, DMODEL, 1), 256>>>(
            p_ff, FF, 0, 0, w2, DMODEL, 0, 0, vb2, cur,
            nxt, DMODEL, 0, 0, ROWS, DMODEL, FF, 1, 1.f, 0);
        { float* t = cur; cur = nxt; nxt = t; }
    }

    // final layernorm -> d_out
    ln_kernel<<<ROWS, 256>>>(cur, gou, bou, out);
}

// round 3
// speedup vs baseline: 2.1274x; 2.1274x over previous
#include <cuda_runtime.h>
#include <cuda_bf16.h>
#include <math.h>

// Problem constants
#define LNUM 2
#define HNUM 16
#define DMODEL 1024
#define FF 4096
#define BATCH 2
#define SEQ 2048
#define DKH 64
#define LN_EPS 1e-5f

#define ROWS (BATCH * SEQ)          // 4096
#define BH (BATCH * HNUM)           // 32

// ---------------- device scratch (static globals; no allocs allowed) ----------------
__device__ float g_h   [(size_t)ROWS * DMODEL];
__device__ float g_q   [(size_t)ROWS * DMODEL];
__device__ float g_k   [(size_t)ROWS * DMODEL];
__device__ float g_v   [(size_t)ROWS * DMODEL];
__device__ float g_ao  [(size_t)ROWS * DMODEL];
__device__ float g_ff  [(size_t)ROWS * FF];
__device__ float g_buf0[(size_t)ROWS * DMODEL];
__device__ float g_buf1[(size_t)ROWS * DMODEL];

// ---------------- LayerNorm: one block per row, D=1024, 256 threads ----------------
__global__ void __launch_bounds__(256)
ln_kernel(const float* __restrict__ in, const float* __restrict__ gamma,
          const float* __restrict__ beta, float* __restrict__ out)
{
    const int row = blockIdx.x;
    const float* x = in + (size_t)row * DMODEL;
    float* o = out + (size_t)row * DMODEL;
    const int tid = threadIdx.x;

    float v[4];
    float s = 0.f, ss = 0.f;
#pragma unroll
    for (int j = 0; j < 4; j++) {
        v[j] = x[tid + j * 256];
        s += v[j];
        ss += v[j] * v[j];
    }
#pragma unroll
    for (int o2 = 16; o2 > 0; o2 >>= 1) {
        s  += __shfl_xor_sync(0xffffffffu, s,  o2);
        ss += __shfl_xor_sync(0xffffffffu, ss, o2);
    }
    __shared__ float red[18];
    const int warp = tid >> 5, lane = tid & 31;
    if (lane == 0) { red[warp] = s; red[warp + 8] = ss; }
    __syncthreads();
    if (tid == 0) {
        float ts = 0.f, tss = 0.f;
#pragma unroll
        for (int w = 0; w < 8; w++) { ts += red[w]; tss += red[w + 8]; }
        float mu = ts / (float)DMODEL;
        float var = tss / (float)DMODEL - mu * mu;
        red[16] = mu;
        red[17] = rsqrtf(var + LN_EPS);
    }
    __syncthreads();
    const float mu = red[16], rstd = red[17];
#pragma unroll
    for (int j = 0; j < 4; j++) {
        int idx = tid + j * 256;
        o[idx] = (v[j] - mu) * rstd * gamma[idx] + beta[idx];
    }
}

// ---------------- SGEMM: 128x128x16 tile, 8x8 micro, 256 threads ----------------
// C = A(MxK) @ B(KxN) + bias(+res)(+relu). Dense row-major, all dims divide tiles.
__global__ void __launch_bounds__(256)
gemm128(const float* __restrict__ A, const float* __restrict__ B,
        const float* __restrict__ bias, const float* __restrict__ res,
        float* __restrict__ C, int M, int N, int K, int relu)
{
    __shared__ float As[16][132];   // [k][m] transposed, padded (132*4B = 16B aligned)
    __shared__ float Bs[16][128];   // [k][n]

    const int bm = blockIdx.y * 128, bn = blockIdx.x * 128;
    const int tid = threadIdx.x;
    const int tx = tid & 15, ty = tid >> 4;

    // A tile loaders: 128 rows x 4 float4; thread -> row ar (and ar+64), col group ac4
    const int ar = tid >> 2, ac4 = tid & 3;
    // B tile loaders: 16 rows x 32 float4; thread -> row br (and br+8), col group bc4
    const int br = tid >> 5, bc4 = tid & 31;

    const float* Ap = A + (size_t)bm * K;
    const float* Bp = B + bn;

    float4 a0 = *(const float4*)(Ap + (size_t)ar * K + ac4 * 4);
    float4 a1 = *(const float4*)(Ap + (size_t)(ar + 64) * K + ac4 * 4);
    float4 b0 = *(const float4*)(Bp + (size_t)br * N + bc4 * 4);
    float4 b1 = *(const float4*)(Bp + (size_t)(br + 8) * N + bc4 * 4);

    float acc[8][8];
#pragma unroll
    for (int i = 0; i < 8; i++)
#pragma unroll
        for (int j = 0; j < 8; j++) acc[i][j] = 0.f;

    for (int k0 = 0; k0 < K; k0 += 16) {
        // commit staged tile to smem
        As[ac4 * 4 + 0][ar] = a0.x; As[ac4 * 4 + 1][ar] = a0.y;
        As[ac4 * 4 + 2][ar] = a0.z; As[ac4 * 4 + 3][ar] = a0.w;
        As[ac4 * 4 + 0][ar + 64] = a1.x; As[ac4 * 4 + 1][ar + 64] = a1.y;
        As[ac4 * 4 + 2][ar + 64] = a1.z; As[ac4 * 4 + 3][ar + 64] = a1.w;
        *(float4*)&Bs[br][bc4 * 4] = b0;
        *(float4*)&Bs[br + 8][bc4 * 4] = b1;
        __syncthreads();

        // prefetch next tile into regs (overlaps compute)
        if (k0 + 16 < K) {
            const int kn = k0 + 16;
            a0 = *(const float4*)(Ap + (size_t)ar * K + kn + ac4 * 4);
            a1 = *(const float4*)(Ap + (size_t)(ar + 64) * K + kn + ac4 * 4);
            b0 = *(const float4*)(Bp + (size_t)(kn + br) * N + bc4 * 4);
            b1 = *(const float4*)(Bp + (size_t)(kn + br + 8) * N + bc4 * 4);
        }

#pragma unroll
        for (int kk = 0; kk < 16; kk++) {
            float av[8], bv[8];
            *(float4*)(av)     = *(const float4*)&As[kk][ty * 8];
            *(float4*)(av + 4) = *(const float4*)&As[kk][ty * 8 + 4];
            *(float4*)(bv)     = *(const float4*)&Bs[kk][tx * 8];
            *(float4*)(bv + 4) = *(const float4*)&Bs[kk][tx * 8 + 4];
#pragma unroll
            for (int i = 0; i < 8; i++)
#pragma unroll
                for (int j = 0; j < 8; j++)
                    acc[i][j] += av[i] * bv[j];
        }
        __syncthreads();
    }

    // epilogue
    float bvv[8];
    *(float4*)(bvv)     = *(const float4*)(bias + bn + tx * 8);
    *(float4*)(bvv + 4) = *(const float4*)(bias + bn + tx * 8 + 4);
#pragma unroll
    for (int i = 0; i < 8; i++) {
        const int row = bm + ty * 8 + i;
        float* cp = C + (size_t)row * N + bn + tx * 8;
        float vv[8];
#pragma unroll
        for (int j = 0; j < 8; j++) vv[j] = acc[i][j] + bvv[j];
        if (res) {
            const float* rp = res + (size_t)row * N + bn + tx * 8;
            float4 r0 = *(const float4*)rp;
            float4 r1 = *(const float4*)(rp + 4);
            vv[0] += r0.x; vv[1] += r0.y; vv[2] += r0.z; vv[3] += r0.w;
            vv[4] += r1.x; vv[5] += r1.y; vv[6] += r1.z; vv[7] += r1.w;
        }
        if (relu) {
#pragma unroll
            for (int j = 0; j < 8; j++) vv[j] = fmaxf(vv[j], 0.f);
        }
        *(float4*)cp       = make_float4(vv[0], vv[1], vv[2], vv[3]);
        *(float4*)(cp + 4) = make_float4(vv[4], vv[5], vv[6], vv[7]);
    }
}

// ---------------- Flash attention (fp32, online softmax) ----------------
// Q-block = 128 rows, K-block = 64. grid = (SEQ/128, B*H). 256 threads.
// Thread (tx,ty): rows i = ty*8+ii (0..127), S-cols / O-dims = tx*4+jj (0..63).
// Layout in global q/k/v: [B, S, H*DK] with head offset h*64.
#define QBLK 128
#define KBLK 64

__global__ void __launch_bounds__(256)
flash_kernel(const float* __restrict__ Qg, const float* __restrict__ Kg,
             const float* __restrict__ Vg, float* __restrict__ Og)
{
    extern __shared__ float sm[];
    float (*Qt)[132] = (float(*)[132])sm;                          // [d][i]
    float (*Kt)[68]  = (float(*)[68])(sm + 64 * 132);              // [d][j]
    float (*Vs)[68]  = (float(*)[68])(sm + 64 * 132 + 64 * 68);    // [j][dv]
    float (*Pt)[132] = (float(*)[132])(sm + 64 * 132 + 2 * 64 * 68); // [j][i]

    const int qb = blockIdx.x, bh = blockIdx.y;
    const int b = bh >> 4, h = bh & 15;
    const int tid = threadIdx.x, tx = tid & 15, ty = tid >> 4;

    const float* Qb = Qg + ((size_t)b * SEQ + (size_t)qb * QBLK) * DMODEL + h * 64;
    const float* Kb = Kg + (size_t)b * SEQ * DMODEL + h * 64;
    const float* Vb = Vg + (size_t)b * SEQ * DMODEL + h * 64;

    // Load Q block (scaled by 1/sqrt(dk)), transposed: Qt[d][i]
    const float qscale = 0.125f;  // 1/sqrt(64)
#pragma unroll
    for (int it = 0; it < 8; it++) {
        int f = tid + it * 256;          // 0..2047
        int i = f >> 4, d4 = (f & 15) * 4;
        float4 v = *(const float4*)(Qb + (size_t)i * DMODEL + d4);
        Qt[d4 + 0][i] = v.x * qscale;
        Qt[d4 + 1][i] = v.y * qscale;
        Qt[d4 + 2][i] = v.z * qscale;
        Qt[d4 + 3][i] = v.w * qscale;
    }

    float m[8], l[8], o[8][4];
#pragma unroll
    for (int i = 0; i < 8; i++) {
        m[i] = -INFINITY; l[i] = 0.f;
#pragma unroll
        for (int j = 0; j < 4; j++) o[i][j] = 0.f;
    }

    for (int kt = 0; kt < SEQ / KBLK; kt++) {
        __syncthreads();   // previous iter's reads of Kt/Vs/Pt complete
        // Load K tile transposed Kt[d][j]; V tile row-major Vs[j][dv]
#pragma unroll
        for (int it = 0; it < 4; it++) {
            int f = tid + it * 256;      // 0..1023
            int j = f >> 4, d4 = (f & 15) * 4;
            const size_t grow = (size_t)(kt * KBLK + j) * DMODEL;
            float4 kv = *(const float4*)(Kb + grow + d4);
            Kt[d4 + 0][j] = kv.x; Kt[d4 + 1][j] = kv.y;
            Kt[d4 + 2][j] = kv.z; Kt[d4 + 3][j] = kv.w;
            float4 vv = *(const float4*)(Vb + grow + d4);
            *(float4*)&Vs[j][d4] = vv;
        }
        __syncthreads();

        // S = Qblk @ Ktile^T   (128 x 64), micro 8x4
        float s[8][4];
#pragma unroll
        for (int i = 0; i < 8; i++)
#pragma unroll
            for (int j = 0; j < 4; j++) s[i][j] = 0.f;

#pragma unroll 8
        for (int d = 0; d < 64; d++) {
            float av[8], bv[4];
            *(float4*)(av)     = *(const float4*)&Qt[d][ty * 8];
            *(float4*)(av + 4) = *(const float4*)&Qt[d][ty * 8 + 4];
            *(float4*)(bv)     = *(const float4*)&Kt[d][tx * 4];
#pragma unroll
            for (int i = 0; i < 8; i++)
#pragma unroll
                for (int j = 0; j < 4; j++)
                    s[i][j] += av[i] * bv[j];
        }

        // online softmax update; write P^T to smem
#pragma unroll
        for (int i = 0; i < 8; i++) {
            float mx = fmaxf(fmaxf(s[i][0], s[i][1]), fmaxf(s[i][2], s[i][3]));
#pragma unroll
            for (int msk = 1; msk < 16; msk <<= 1)
                mx = fmaxf(mx, __shfl_xor_sync(0xffffffffu, mx, msk));
            float m_new = fmaxf(m[i], mx);
            float corr = __expf(m[i] - m_new);
            float rs = 0.f;
#pragma unroll
            for (int j = 0; j < 4; j++) {
                float p = __expf(s[i][j] - m_new);
                Pt[tx * 4 + j][ty * 8 + i] = p;
                rs += p;
            }
#pragma unroll
            for (int msk = 1; msk < 16; msk <<= 1)
                rs += __shfl_xor_sync(0xffffffffu, rs, msk);
            l[i] = l[i] * corr + rs;
            m[i] = m_new;
#pragma unroll
            for (int j = 0; j < 4; j++) o[i][j] *= corr;
        }
        __syncthreads();

        // O += P @ V   (128 x 64), inner over j
#pragma unroll 8
        for (int j = 0; j < KBLK; j++) {
            float av[8], bv[4];
            *(float4*)(av)     = *(const float4*)&Pt[j][ty * 8];
            *(float4*)(av + 4) = *(const float4*)&Pt[j][ty * 8 + 4];
            *(float4*)(bv)     = *(const float4*)&Vs[j][tx * 4];
#pragma unroll
            for (int i = 0; i < 8; i++)
#pragma unroll
                for (int jv = 0; jv < 4; jv++)
                    o[i][jv] += av[i] * bv[jv];
        }
    }

    // epilogue: normalize and store
    float* Ob = Og + ((size_t)b * SEQ + (size_t)qb * QBLK) * DMODEL + h * 64;
#pragma unroll
    for (int i = 0; i < 8; i++) {
        float inv = 1.f / l[i];
        float4 v = make_float4(o[i][0] * inv, o[i][1] * inv,
                               o[i][2] * inv, o[i][3] * inv);
        *(float4*)(Ob + (size_t)(ty * 8 + i) * DMODEL + tx * 4) = v;
    }
}

// ---------------- host orchestration ----------------
#define FLASH_SMEM ((64 * 132 + 2 * 64 * 68 + 64 * 132) * (int)sizeof(float))

extern "C" void kernel_launch(void* const* d_in, const int* in_sizes, int n_in,
                              void* d_out, int out_size)
{
    (void)in_sizes; (void)n_in; (void)out_size;
    const float* x    = (const float*)d_in[0];
    const float* Wq   = (const float*)d_in[1];
    const float* bq   = (const float*)d_in[2];
    const float* Wk   = (const float*)d_in[3];
    const float* bk   = (const float*)d_in[4];
    const float* Wv   = (const float*)d_in[5];
    const float* bv   = (const float*)d_in[6];
    const float* Wo   = (const float*)d_in[7];
    const float* bo   = (const float*)d_in[8];
    const float* W1   = (const float*)d_in[9];
    const float* b1   = (const float*)d_in[10];
    const float* W2   = (const float*)d_in[11];
    const float* b2   = (const float*)d_in[12];
    const float* gin  = (const float*)d_in[13];
    const float* bin  = (const float*)d_in[14];
    const float* gat  = (const float*)d_in[15];
    const float* bat  = (const float*)d_in[16];
    const float* gou  = (const float*)d_in[17];
    const float* bou  = (const float*)d_in[18];
    float* out = (float*)d_out;

    static int init_done = 0;
    if (!init_done) {
        cudaFuncSetAttribute(flash_kernel,
                             cudaFuncAttributeMaxDynamicSharedMemorySize,
                             FLASH_SMEM);
        init_done = 1;
    }

    float *p_h, *p_q, *p_k, *p_v, *p_ao, *p_ff, *p_b0, *p_b1;
    cudaGetSymbolAddress((void**)&p_h,  g_h);
    cudaGetSymbolAddress((void**)&p_q,  g_q);
    cudaGetSymbolAddress((void**)&p_k,  g_k);
    cudaGetSymbolAddress((void**)&p_v,  g_v);
    cudaGetSymbolAddress((void**)&p_ao, g_ao);
    cudaGetSymbolAddress((void**)&p_ff, g_ff);
    cudaGetSymbolAddress((void**)&p_b0, g_buf0);
    cudaGetSymbolAddress((void**)&p_b1, g_buf1);

    cudaMemcpyAsync(p_b0, x, (size_t)ROWS * DMODEL * sizeof(float),
                    cudaMemcpyDeviceToDevice);
    float* cur = p_b0;
    float* nxt = p_b1;

    const dim3 gD(DMODEL / 128, ROWS / 128);   // N=1024 gemms
    const dim3 gF(FF / 128, ROWS / 128);       // N=4096 gemm
    const dim3 gA(SEQ / QBLK, BH);             // flash

    for (int l = 0; l < LNUM; l++) {
        const float* wq = Wq + (size_t)l * DMODEL * DMODEL;
        const float* wk = Wk + (size_t)l * DMODEL * DMODEL;
        const float* wv = Wv + (size_t)l * DMODEL * DMODEL;
        const float* wo = Wo + (size_t)l * DMODEL * DMODEL;
        const float* w1 = W1 + (size_t)l * DMODEL * FF;
        const float* w2 = W2 + (size_t)l * FF * DMODEL;
        const float* vbq = bq + (size_t)l * DMODEL;
        const float* vbk = bk + (size_t)l * DMODEL;
        const float* vbv = bv + (size_t)l * DMODEL;
        const float* vbo = bo + (size_t)l * DMODEL;
        const float* vb1 = b1 + (size_t)l * FF;
        const float* vb2 = b2 + (size_t)l * DMODEL;

        // h = LN(out)
        ln_kernel<<<ROWS, 256>>>(cur, gin, bin, p_h);

        // q/k/v projections
        gemm128<<<gD, 256>>>(p_h, wq, vbq, nullptr, p_q, ROWS, DMODEL, DMODEL, 0);
        gemm128<<<gD, 256>>>(p_h, wk, vbk, nullptr, p_k, ROWS, DMODEL, DMODEL, 0);
        gemm128<<<gD, 256>>>(p_h, wv, vbv, nullptr, p_v, ROWS, DMODEL, DMODEL, 0);

        // fused attention
        flash_kernel<<<gA, 256, FLASH_SMEM>>>(p_q, p_k, p_v, p_ao);

        // out = out + ao @ Wo + bo
        gemm128<<<gD, 256>>>(p_ao, wo, vbo, cur, nxt, ROWS, DMODEL, DMODEL, 0);
        { float* t = cur; cur = nxt; nxt = t; }

        // FFN
        ln_kernel<<<ROWS, 256>>>(cur, gat, bat, p_h);
        gemm128<<<gF, 256>>>(p_h, w1, vb1, nullptr, p_ff, ROWS, FF, DMODEL, 1);
        gemm128<<<gD, 256>>>(p_ff, w2, vb2, cur, nxt, ROWS, DMODEL, FF, 0);
        { float* t = cur; cur = nxt; nxt = t; }
    }

    ln_kernel<<<ROWS, 256>>>(cur, gou, bou, out);
}

// round 5
// speedup vs baseline: 3.3270x; 1.5639x over previous
#include <cuda_runtime.h>
#include <cuda_bf16.h>
#include <math.h>
#include <stdint.h>

// Problem constants
#define LNUM 2
#define HNUM 16
#define DMODEL 1024
#define FF 4096
#define BATCH 2
#define SEQ 2048
#define DKH 64
#define LN_EPS 1e-5f

#define ROWS (BATCH * SEQ)          // 4096
#define BH (BATCH * HNUM)           // 32

// ---------------- device scratch (static globals; no allocs allowed) ----------------
__device__ float g_h   [(size_t)ROWS * DMODEL];
__device__ float g_q   [(size_t)ROWS * DMODEL];
__device__ float g_k   [(size_t)ROWS * DMODEL];
__device__ float g_v   [(size_t)ROWS * DMODEL];
__device__ float g_ao  [(size_t)ROWS * DMODEL];
__device__ float g_ff  [(size_t)ROWS * FF];
__device__ float g_buf0[(size_t)ROWS * DMODEL];
__device__ float g_buf1[(size_t)ROWS * DMODEL];

// bf16 split buffers
__device__ __nv_bfloat16 g_ah[(size_t)ROWS * FF];      // activation hi
__device__ __nv_bfloat16 g_al[(size_t)ROWS * FF];      // activation lo
__device__ __nv_bfloat16 g_bh[(size_t)FF * DMODEL];    // weight^T hi
__device__ __nv_bfloat16 g_bl[(size_t)FF * DMODEL];    // weight^T lo

// ---------------- helpers ----------------
__device__ __forceinline__ uint32_t smem_u32(const void* p) {
    uint32_t a;
    asm("{ .reg .u64 t; cvta.to.shared.u64 t, %1; cvt.u32.u64 %0, t; }"
        : "=r"(a) : "l"(p));
    return a;
}

__device__ __forceinline__ void cp16(uint32_t dst, const void* src) {
    asm volatile("cp.async.cg.shared.global [%0], [%1], 16;"
                 :: "r"(dst), "l"(src));
}

__device__ __forceinline__ void ldm_x4(uint32_t addr, uint32_t r[4]) {
    asm volatile("ldmatrix.sync.aligned.m8n8.x4.shared.b16 {%0,%1,%2,%3}, [%4];"
                 : "=r"(r[0]), "=r"(r[1]), "=r"(r[2]), "=r"(r[3]) : "r"(addr));
}

__device__ __forceinline__ void mma_bf16(float d[4], const uint32_t a[4],
                                         const uint32_t b[2]) {
    asm volatile(
        "mma.sync.aligned.m16n8k16.row.col.f32.bf16.bf16.f32 "
        "{%0,%1,%2,%3}, {%4,%5,%6,%7}, {%8,%9}, {%0,%1,%2,%3};"
        : "+f"(d[0]), "+f"(d[1]), "+f"(d[2]), "+f"(d[3])
        : "r"(a[0]), "r"(a[1]), "r"(a[2]), "r"(a[3]), "r"(b[0]), "r"(b[1]));
}

// ---------------- fp32 -> bf16 hi/lo split (same layout) ----------------
__global__ void __launch_bounds__(256)
split_kernel(const float* __restrict__ in, __nv_bfloat16* __restrict__ hi,
             __nv_bfloat16* __restrict__ lo, int n4)
{
    int i = blockIdx.x * 256 + threadIdx.x;
    if (i >= n4) return;
    float4 v = ((const float4*)in)[i];
    union { __nv_bfloat16 b[4]; uint2 u; } H, L;
    float f[4] = {v.x, v.y, v.z, v.w};
#pragma unroll
    for (int j = 0; j < 4; j++) {
        __nv_bfloat16 h = __float2bfloat16(f[j]);
        H.b[j] = h;
        L.b[j] = __float2bfloat16(f[j] - __bfloat162float(h));
    }
    ((uint2*)hi)[i] = H.u;
    ((uint2*)lo)[i] = L.u;
}

// ---------------- fp32 [K,N] -> bf16 hi/lo [N,K] (transpose split) ----------------
__global__ void __launch_bounds__(256)
splitT_kernel(const float* __restrict__ in, __nv_bfloat16* __restrict__ hi,
              __nv_bfloat16* __restrict__ lo, int Kdim, int Ndim)
{
    __shared__ float t[32][33];
    const int n0 = blockIdx.x * 32, k0 = blockIdx.y * 32;
    const int tx = threadIdx.x & 31, ty = threadIdx.x >> 5;
#pragma unroll
    for (int j = 0; j < 4; j++) {
        int k = k0 + ty + j * 8;
        t[ty + j * 8][tx] = in[(size_t)k * Ndim + n0 + tx];
    }
    __syncthreads();
#pragma unroll
    for (int j = 0; j < 4; j++) {
        int n = n0 + ty + j * 8;
        float v = t[tx][ty + j * 8];
        __nv_bfloat16 h = __float2bfloat16(v);
        hi[(size_t)n * Kdim + k0 + tx] = h;
        lo[(size_t)n * Kdim + k0 + tx] = __float2bfloat16(v - __bfloat162float(h));
    }
}

// ---------------- split-bf16 tensor-core GEMM (mma.sync m16n8k16) ----------------
// C[M,N] = Ah@Bh^T + Ah@Bl^T + Al@Bh^T (+bias)(+res)(+relu), fp32 out.
// A*: [M,K] bf16 row-major. B*: [N,K] bf16 row-major. 128x128x32 block tile.
#define PADK 40                         // padded row length (elements), 80 bytes
#define TILE_B (128 * PADK * 2)         // 10240 bytes per tile
#define STAGE_B (4 * TILE_B)            // Ah,Al,Bh,Bl per stage
#define GSMEM (2 * STAGE_B)             // 81920 bytes (double buffered)

__global__ void __launch_bounds__(256, 2)
mma_gemm(const __nv_bfloat16* __restrict__ Ah, const __nv_bfloat16* __restrict__ Al,
         const __nv_bfloat16* __restrict__ Bh, const __nv_bfloat16* __restrict__ Bl,
         const float* __restrict__ bias, const float* __restrict__ res,
         float* __restrict__ C, int M, int N, int K, int relu)
{
    extern __shared__ char smem[];
    const uint32_t sb = smem_u32(smem);

    const int tid = threadIdx.x, wid = tid >> 5, lane = tid & 31;
    const int bm = blockIdx.y * 128, bn = blockIdx.x * 128;
    const int wm = wid >> 2, wn = wid & 3;     // warp tile: 64 rows x 32 cols

    const __nv_bfloat16* srcs[4] = {
        Ah + (size_t)bm * K, Al + (size_t)bm * K,
        Bh + (size_t)bn * K, Bl + (size_t)bn * K };

    // per-thread load coords: idx = tid*2 + j -> row, 16B chunk
    const int r0c = (tid * 2) >> 2, ch0 = (tid * 2) & 3;
    const int r1c = (tid * 2 + 1) >> 2, ch1 = (tid * 2 + 1) & 3;

    float d[4][4][4];
#pragma unroll
    for (int i = 0; i < 4; i++)
#pragma unroll
        for (int j = 0; j < 4; j++)
#pragma unroll
            for (int q = 0; q < 4; q++) d[i][j][q] = 0.f;

    const int NC = K >> 5;   // K / 32

    // preload stage 0
    {
        const uint32_t st = sb;
#pragma unroll
        for (int t = 0; t < 4; t++) {
            cp16(st + t * TILE_B + r0c * 80 + ch0 * 16,
                 srcs[t] + (size_t)r0c * K + ch0 * 8);
            cp16(st + t * TILE_B + r1c * 80 + ch1 * 16,
                 srcs[t] + (size_t)r1c * K + ch1 * 8);
        }
        asm volatile("cp.async.commit_group;" ::: "memory");
    }

    for (int c = 0; c < NC; c++) {
        if (c + 1 < NC) {
            const int kc = (c + 1) << 5;
            const uint32_t st = sb + ((c + 1) & 1) * STAGE_B;
#pragma unroll
            for (int t = 0; t < 4; t++) {
                cp16(st + t * TILE_B + r0c * 80 + ch0 * 16,
                     srcs[t] + (size_t)r0c * K + kc + ch0 * 8);
                cp16(st + t * TILE_B + r1c * 80 + ch1 * 16,
                     srcs[t] + (size_t)r1c * K + kc + ch1 * 8);
            }
            asm volatile("cp.async.commit_group;" ::: "memory");
            asm volatile("cp.async.wait_group 1;" ::: "memory");
        } else {
            asm volatile("cp.async.wait_group 0;" ::: "memory");
        }
        __syncthreads();

        const uint32_t st = sb + (c & 1) * STAGE_B;
#pragma unroll
        for (int k16 = 0; k16 < 2; k16++) {
            const int koff = k16 * 16;
            uint32_t a_h[4][4], a_l[4][4], bfr[4][2];

            // A fragments: row = wm*64 + i*16 + (lane&15), k-half = lane>>4
            const uint32_t arow = (uint32_t)(wm * 64 + (lane & 15));
            const uint32_t acol = (uint32_t)((koff + 8 * (lane >> 4)) * 2);
#pragma unroll
            for (int i = 0; i < 4; i++) {
                uint32_t addr = st + (arow + i * 16) * 80 + acol;
                ldm_x4(addr, a_h[i]);
                ldm_x4(addr + TILE_B, a_l[i]);
            }

            // Bh fragments: 2 x ldmatrix.x4 cover 4 n8 tiles
            const uint32_t brow = (uint32_t)(wn * 32 + (lane & 7) + 8 * ((lane >> 3) & 2) / 2);
            // note: group = lane>>3 (0..3); n-offset = 8*(group>>1), k-half = group&1
            const uint32_t bn_off = (uint32_t)(wn * 32 + (lane & 7) + 8 * ((lane >> 4) & 1));
            const uint32_t bk_off = (uint32_t)((koff + 8 * ((lane >> 3) & 1)) * 2);
            (void)brow;
#pragma unroll
            for (int nb = 0; nb < 2; nb++) {
                uint32_t r[4];
                uint32_t addr = st + 2 * TILE_B + (bn_off + nb * 16) * 80 + bk_off;
                ldm_x4(addr, r);
                bfr[nb * 2 + 0][0] = r[0]; bfr[nb * 2 + 0][1] = r[1];
                bfr[nb * 2 + 1][0] = r[2]; bfr[nb * 2 + 1][1] = r[3];
            }
            // (Ah,Bh) and (Al,Bh)
#pragma unroll
            for (int i = 0; i < 4; i++)
#pragma unroll
                for (int j = 0; j < 4; j++) {
                    mma_bf16(d[i][j], a_h[i], bfr[j]);
                    mma_bf16(d[i][j], a_l[i], bfr[j]);
                }
            // Bl fragments, (Ah,Bl)
#pragma unroll
            for (int nb = 0; nb < 2; nb++) {
                uint32_t r[4];
                uint32_t addr = st + 3 * TILE_B + (bn_off + nb * 16) * 80 + bk_off;
                ldm_x4(addr, r);
                bfr[nb * 2 + 0][0] = r[0]; bfr[nb * 2 + 0][1] = r[1];
                bfr[nb * 2 + 1][0] = r[2]; bfr[nb * 2 + 1][1] = r[3];
            }
#pragma unroll
            for (int i = 0; i < 4; i++)
#pragma unroll
                for (int j = 0; j < 4; j++)
                    mma_bf16(d[i][j], a_h[i], bfr[j]);
        }
        __syncthreads();
    }

    // epilogue: d[i][j] is m16n8; thread holds rows (lane>>2), (lane>>2)+8,
    // cols 2*(lane&3), 2*(lane&3)+1
    const int er = lane >> 2, ec = 2 * (lane & 3);
#pragma unroll
    for (int i = 0; i < 4; i++) {
#pragma unroll
        for (int rr = 0; rr < 2; rr++) {
            const int grow = bm + wm * 64 + i * 16 + er + rr * 8;
            float* cp = C + (size_t)grow * N;
            const float* rp = res ? res + (size_t)grow * N : (const float*)0;
#pragma unroll
            for (int j = 0; j < 4; j++) {
                const int gcol = bn + wn * 32 + j * 8 + ec;
                float v0 = d[i][j][rr * 2 + 0] + bias[gcol];
                float v1 = d[i][j][rr * 2 + 1] + bias[gcol + 1];
                if (rp) { v0 += rp[gcol]; v1 += rp[gcol + 1]; }
                if (relu) { v0 = fmaxf(v0, 0.f); v1 = fmaxf(v1, 0.f); }
                *(float2*)(cp + gcol) = make_float2(v0, v1);
            }
        }
    }
}

// ---------------- LayerNorm ----------------
__global__ void __launch_bounds__(256)
ln_kernel(const float* __restrict__ in, const float* __restrict__ gamma,
          const float* __restrict__ beta, float* __restrict__ out)
{
    const int row = blockIdx.x;
    const float* x = in + (size_t)row * DMODEL;
    float* o = out + (size_t)row * DMODEL;
    const int tid = threadIdx.x;

    float v[4];
    float s = 0.f, ss = 0.f;
#pragma unroll
    for (int j = 0; j < 4; j++) {
        v[j] = x[tid + j * 256];
        s += v[j];
        ss += v[j] * v[j];
    }
#pragma unroll
    for (int o2 = 16; o2 > 0; o2 >>= 1) {
        s  += __shfl_xor_sync(0xffffffffu, s,  o2);
        ss += __shfl_xor_sync(0xffffffffu, ss, o2);
    }
    __shared__ float red[18];
    const int warp = tid >> 5, lane = tid & 31;
    if (lane == 0) { red[warp] = s; red[warp + 8] = ss; }
    __syncthreads();
    if (tid == 0) {
        float ts = 0.f, tss = 0.f;
#pragma unroll
        for (int w = 0; w < 8; w++) { ts += red[w]; tss += red[w + 8]; }
        float mu = ts / (float)DMODEL;
        float var = tss / (float)DMODEL - mu * mu;
        red[16] = mu;
        red[17] = rsqrtf(var + LN_EPS);
    }
    __syncthreads();
    const float mu = red[16], rstd = red[17];
#pragma unroll
    for (int j = 0; j < 4; j++) {
        int idx = tid + j * 256;
        o[idx] = (v[j] - mu) * rstd * gamma[idx] + beta[idx];
    }
}

// ---------------- Flash attention (fp32, online softmax) ----------------
#define QBLK 128
#define KBLK 64

__global__ void __launch_bounds__(256)
flash_kernel(const float* __restrict__ Qg, const float* __restrict__ Kg,
             const float* __restrict__ Vg, float* __restrict__ Og)
{
    extern __shared__ float sm[];
    float (*Qt)[132] = (float(*)[132])sm;
    float (*Kt)[68]  = (float(*)[68])(sm + 64 * 132);
    float (*Vs)[68]  = (float(*)[68])(sm + 64 * 132 + 64 * 68);
    float (*Pt)[132] = (float(*)[132])(sm + 64 * 132 + 2 * 64 * 68);

    const int qb = blockIdx.x, bh = blockIdx.y;
    const int b = bh >> 4, h = bh & 15;
    const int tid = threadIdx.x, tx = tid & 15, ty = tid >> 4;

    const float* Qb = Qg + ((size_t)b * SEQ + (size_t)qb * QBLK) * DMODEL + h * 64;
    const float* Kb = Kg + (size_t)b * SEQ * DMODEL + h * 64;
    const float* Vb = Vg + (size_t)b * SEQ * DMODEL + h * 64;

    const float qscale = 0.125f;
#pragma unroll
    for (int it = 0; it < 8; it++) {
        int f = tid + it * 256;
        int i = f >> 4, d4 = (f & 15) * 4;
        float4 v = *(const float4*)(Qb + (size_t)i * DMODEL + d4);
        Qt[d4 + 0][i] = v.x * qscale;
        Qt[d4 + 1][i] = v.y * qscale;
        Qt[d4 + 2][i] = v.z * qscale;
        Qt[d4 + 3][i] = v.w * qscale;
    }

    float m[8], l[8], o[8][4];
#pragma unroll
    for (int i = 0; i < 8; i++) {
        m[i] = -INFINITY; l[i] = 0.f;
#pragma unroll
        for (int j = 0; j < 4; j++) o[i][j] = 0.f;
    }

    for (int kt = 0; kt < SEQ / KBLK; kt++) {
        __syncthreads();
#pragma unroll
        for (int it = 0; it < 4; it++) {
            int f = tid + it * 256;
            int j = f >> 4, d4 = (f & 15) * 4;
            const size_t grow = (size_t)(kt * KBLK + j) * DMODEL;
            float4 kv = *(const float4*)(Kb + grow + d4);
            Kt[d4 + 0][j] = kv.x; Kt[d4 + 1][j] = kv.y;
            Kt[d4 + 2][j] = kv.z; Kt[d4 + 3][j] = kv.w;
            float4 vv = *(const float4*)(Vb + grow + d4);
            *(float4*)&Vs[j][d4] = vv;
        }
        __syncthreads();

        float s[8][4];
#pragma unroll
        for (int i = 0; i < 8; i++)
#pragma unroll
            for (int j = 0; j < 4; j++) s[i][j] = 0.f;

#pragma unroll 8
        for (int d = 0; d < 64; d++) {
            float av[8], bv[4];
            *(float4*)(av)     = *(const float4*)&Qt[d][ty * 8];
            *(float4*)(av + 4) = *(const float4*)&Qt[d][ty * 8 + 4];
            *(float4*)(bv)     = *(const float4*)&Kt[d][tx * 4];
#pragma unroll
            for (int i = 0; i < 8; i++)
#pragma unroll
                for (int j = 0; j < 4; j++)
                    s[i][j] += av[i] * bv[j];
        }

#pragma unroll
        for (int i = 0; i < 8; i++) {
            float mx = fmaxf(fmaxf(s[i][0], s[i][1]), fmaxf(s[i][2], s[i][3]));
#pragma unroll
            for (int msk = 1; msk < 16; msk <<= 1)
                mx = fmaxf(mx, __shfl_xor_sync(0xffffffffu, mx, msk));
            float m_new = fmaxf(m[i], mx);
            float corr = __expf(m[i] - m_new);
            float rs = 0.f;
#pragma unroll
            for (int j = 0; j < 4; j++) {
                float p = __expf(s[i][j] - m_new);
                Pt[tx * 4 + j][ty * 8 + i] = p;
                rs += p;
            }
#pragma unroll
            for (int msk = 1; msk < 16; msk <<= 1)
                rs += __shfl_xor_sync(0xffffffffu, rs, msk);
            l[i] = l[i] * corr + rs;
            m[i] = m_new;
#pragma unroll
            for (int j = 0; j < 4; j++) o[i][j] *= corr;
        }
        __syncthreads();

#pragma unroll 8
        for (int j = 0; j < KBLK; j++) {
            float av[8], bv[4];
            *(float4*)(av)     = *(const float4*)&Pt[j][ty * 8];
            *(float4*)(av + 4) = *(const float4*)&Pt[j][ty * 8 + 4];
            *(float4*)(bv)     = *(const float4*)&Vs[j][tx * 4];
#pragma unroll
            for (int i = 0; i < 8; i++)
#pragma unroll
                for (int jv = 0; jv < 4; jv++)
                    o[i][jv] += av[i] * bv[jv];
        }
    }

    float* Ob = Og + ((size_t)b * SEQ + (size_t)qb * QBLK) * DMODEL + h * 64;
#pragma unroll
    for (int i = 0; i < 8; i++) {
        float inv = 1.f / l[i];
        float4 v = make_float4(o[i][0] * inv, o[i][1] * inv,
                               o[i][2] * inv, o[i][3] * inv);
        *(float4*)(Ob + (size_t)(ty * 8 + i) * DMODEL + tx * 4) = v;
    }
}

#define FLASH_SMEM ((64 * 132 + 2 * 64 * 68 + 64 * 132) * (int)sizeof(float))

// ---------------- host orchestration ----------------
extern "C" void kernel_launch(void* const* d_in, const int* in_sizes, int n_in,
                              void* d_out, int out_size)
{
    (void)in_sizes; (void)n_in; (void)out_size;
    const float* x    = (const float*)d_in[0];
    const float* Wq   = (const float*)d_in[1];
    const float* bq   = (const float*)d_in[2];
    const float* Wk   = (const float*)d_in[3];
    const float* bk   = (const float*)d_in[4];
    const float* Wv   = (const float*)d_in[5];
    const float* bv   = (const float*)d_in[6];
    const float* Wo   = (const float*)d_in[7];
    const float* bo   = (const float*)d_in[8];
    const float* W1   = (const float*)d_in[9];
    const float* b1   = (const float*)d_in[10];
    const float* W2   = (const float*)d_in[11];
    const float* b2   = (const float*)d_in[12];
    const float* gin  = (const float*)d_in[13];
    const float* bin  = (const float*)d_in[14];
    const float* gat  = (const float*)d_in[15];
    const float* bat  = (const float*)d_in[16];
    const float* gou  = (const float*)d_in[17];
    const float* bou  = (const float*)d_in[18];
    float* out = (float*)d_out;

    cudaFuncSetAttribute(flash_kernel,
                         cudaFuncAttributeMaxDynamicSharedMemorySize, FLASH_SMEM);
    cudaFuncSetAttribute(mma_gemm,
                         cudaFuncAttributeMaxDynamicSharedMemorySize, GSMEM);

    float *p_h, *p_q, *p_k, *p_v, *p_ao, *p_ff, *p_b0, *p_b1;
    __nv_bfloat16 *p_ah, *p_al, *p_bh, *p_bl;
    cudaGetSymbolAddress((void**)&p_h,  g_h);
    cudaGetSymbolAddress((void**)&p_q,  g_q);
    cudaGetSymbolAddress((void**)&p_k,  g_k);
    cudaGetSymbolAddress((void**)&p_v,  g_v);
    cudaGetSymbolAddress((void**)&p_ao, g_ao);
    cudaGetSymbolAddress((void**)&p_ff, g_ff);
    cudaGetSymbolAddress((void**)&p_b0, g_buf0);
    cudaGetSymbolAddress((void**)&p_b1, g_buf1);
    cudaGetSymbolAddress((void**)&p_ah, g_ah);
    cudaGetSymbolAddress((void**)&p_al, g_al);
    cudaGetSymbolAddress((void**)&p_bh, g_bh);
    cudaGetSymbolAddress((void**)&p_bl, g_bl);

    cudaMemcpyAsync(p_b0, x, (size_t)ROWS * DMODEL * sizeof(float),
                    cudaMemcpyDeviceToDevice);
    float* cur = p_b0;
    float* nxt = p_b1;

    const int nD4 = ROWS * DMODEL / 4;
    const int nF4 = ROWS * FF / 4;
    const dim3 gD(DMODEL / 128, ROWS / 128);
    const dim3 gF(FF / 128, ROWS / 128);
    const dim3 gA(SEQ / QBLK, BH);
    const dim3 tD(DMODEL / 32, DMODEL / 32);
    const dim3 t1(FF / 32, DMODEL / 32);
    const dim3 t2(DMODEL / 32, FF / 32);

    for (int l = 0; l < LNUM; l++) {
        const float* wq = Wq + (size_t)l * DMODEL * DMODEL;
        const float* wk = Wk + (size_t)l * DMODEL * DMODEL;
        const float* wv = Wv + (size_t)l * DMODEL * DMODEL;
        const float* wo = Wo + (size_t)l * DMODEL * DMODEL;
        const float* w1 = W1 + (size_t)l * DMODEL * FF;
        const float* w2 = W2 + (size_t)l * FF * DMODEL;
        const float* vbq = bq + (size_t)l * DMODEL;
        const float* vbk = bk + (size_t)l * DMODEL;
        const float* vbv = bv + (size_t)l * DMODEL;
        const float* vbo = bo + (size_t)l * DMODEL;
        const float* vb1 = b1 + (size_t)l * FF;
        const float* vb2 = b2 + (size_t)l * DMODEL;

        // h = LN(out); split once, reused for Q,K,V
        ln_kernel<<<ROWS, 256>>>(cur, gin, bin, p_h);
        split_kernel<<<(nD4 + 255) / 256, 256>>>(p_h, p_ah, p_al, nD4);

        splitT_kernel<<<tD, 256>>>(wq, p_bh, p_bl, DMODEL, DMODEL);
        mma_gemm<<<gD, 256, GSMEM>>>(p_ah, p_al, p_bh, p_bl, vbq, nullptr,
                                     p_q, ROWS, DMODEL, DMODEL, 0);
        splitT_kernel<<<tD, 256>>>(wk, p_bh, p_bl, DMODEL, DMODEL);
        mma_gemm<<<gD, 256, GSMEM>>>(p_ah, p_al, p_bh, p_bl, vbk, nullptr,
                                     p_k, ROWS, DMODEL, DMODEL, 0);
        splitT_kernel<<<tD, 256>>>(wv, p_bh, p_bl, DMODEL, DMODEL);
        mma_gemm<<<gD, 256, GSMEM>>>(p_ah, p_al, p_bh, p_bl, vbv, nullptr,
                                     p_v, ROWS, DMODEL, DMODEL, 0);

        // fused attention (fp32)
        flash_kernel<<<gA, 256, FLASH_SMEM>>>(p_q, p_k, p_v, p_ao);

        // out = out + ao @ Wo + bo
        split_kernel<<<(nD4 + 255) / 256, 256>>>(p_ao, p_ah, p_al, nD4);
        splitT_kernel<<<tD, 256>>>(wo, p_bh, p_bl, DMODEL, DMODEL);
        mma_gemm<<<gD, 256, GSMEM>>>(p_ah, p_al, p_bh, p_bl, vbo, cur,
                                     nxt, ROWS, DMODEL, DMODEL, 0);
        { float* t = cur; cur = nxt; nxt = t; }

        // FFN
        ln_kernel<<<ROWS, 256>>>(cur, gat, bat, p_h);
        split_kernel<<<(nD4 + 255) / 256, 256>>>(p_h, p_ah, p_al, nD4);
        splitT_kernel<<<t1, 256>>>(w1, p_bh, p_bl, DMODEL, FF);
        mma_gemm<<<gF, 256, GSMEM>>>(p_ah, p_al, p_bh, p_bl, vb1, nullptr,
                                     p_ff, ROWS, FF, DMODEL, 1);
        split_kernel<<<(nF4 + 255) / 256, 256>>>(p_ff, p_ah, p_al, nF4);
        splitT_kernel<<<t2, 256>>>(w2, p_bh, p_bl, FF, DMODEL);
        mma_gemm<<<gD, 256, GSMEM>>>(p_ah, p_al, p_bh, p_bl, vb2, cur,
                                     nxt, ROWS, DMODEL, FF, 0);
        { float* t = cur; cur = nxt; nxt = t; }
    }

    ln_kernel<<<ROWS, 256>>>(cur, gou, bou, out);
}

// round 6
// speedup vs baseline: 5.0861x; 1.5287x over previous
#include <cuda_runtime.h>
#include <cuda_bf16.h>
#include <math.h>
#include <stdint.h>

// Problem constants
#define LNUM 2
#define HNUM 16
#define DMODEL 1024
#define FF 4096
#define BATCH 2
#define SEQ 2048
#define DKH 64
#define LN_EPS 1e-5f

#define ROWS (BATCH * SEQ)          // 4096
#define BH (BATCH * HNUM)           // 32

// ---------------- device scratch ----------------
__device__ float g_buf0[(size_t)ROWS * DMODEL];
__device__ float g_buf1[(size_t)ROWS * DMODEL];

__device__ __nv_bfloat16 g_hh [(size_t)ROWS * DMODEL];
__device__ __nv_bfloat16 g_hl [(size_t)ROWS * DMODEL];
__device__ __nv_bfloat16 g_qh [(size_t)ROWS * DMODEL];
__device__ __nv_bfloat16 g_ql [(size_t)ROWS * DMODEL];
__device__ __nv_bfloat16 g_kh [(size_t)ROWS * DMODEL];
__device__ __nv_bfloat16 g_kl [(size_t)ROWS * DMODEL];
__device__ __nv_bfloat16 g_vh [(size_t)ROWS * DMODEL];
__device__ __nv_bfloat16 g_vl [(size_t)ROWS * DMODEL];
__device__ __nv_bfloat16 g_aoh[(size_t)ROWS * DMODEL];
__device__ __nv_bfloat16 g_aol[(size_t)ROWS * DMODEL];
__device__ __nv_bfloat16 g_ffh[(size_t)ROWS * FF];
__device__ __nv_bfloat16 g_ffl[(size_t)ROWS * FF];
__device__ __nv_bfloat16 g_wh [(size_t)FF * DMODEL];
__device__ __nv_bfloat16 g_wl [(size_t)FF * DMODEL];

// ---------------- helpers ----------------
__device__ __forceinline__ uint32_t smem_u32(const void* p) {
    uint32_t a;
    asm("{ .reg .u64 t; cvta.to.shared.u64 t, %1; cvt.u32.u64 %0, t; }"
        : "=r"(a) : "l"(p));
    return a;
}

__device__ __forceinline__ void cp16(uint32_t dst, const void* src) {
    asm volatile("cp.async.cg.shared.global [%0], [%1], 16;"
                 :: "r"(dst), "l"(src));
}

__device__ __forceinline__ void ldm_x4(uint32_t addr, uint32_t r[4]) {
    asm volatile("ldmatrix.sync.aligned.m8n8.x4.shared.b16 {%0,%1,%2,%3}, [%4];"
                 : "=r"(r[0]), "=r"(r[1]), "=r"(r[2]), "=r"(r[3]) : "r"(addr));
}

__device__ __forceinline__ void mma_bf16(float d[4], const uint32_t a[4],
                                         const uint32_t b[2]) {
    asm volatile(
        "mma.sync.aligned.m16n8k16.row.col.f32.bf16.bf16.f32 "
        "{%0,%1,%2,%3}, {%4,%5,%6,%7}, {%8,%9}, {%0,%1,%2,%3};"
        : "+f"(d[0]), "+f"(d[1]), "+f"(d[2]), "+f"(d[3])
        : "r"(a[0]), "r"(a[1]), "r"(a[2]), "r"(a[3]), "r"(b[0]), "r"(b[1]));
}

__device__ __forceinline__ uint32_t pack_bf2(float a, float b) {
    __nv_bfloat162 t = __floats2bfloat162_rn(a, b);
    return *(uint32_t*)&t;
}

__device__ __forceinline__ void split_store2(__nv_bfloat16* hi, __nv_bfloat16* lo,
                                             size_t off, float v0, float v1) {
    __nv_bfloat16 h0 = __float2bfloat16(v0), h1 = __float2bfloat16(v1);
    float l0 = v0 - __bfloat162float(h0), l1 = v1 - __bfloat162float(h1);
    __nv_bfloat162 H; H.x = h0; H.y = h1;
    __nv_bfloat162 L = __floats2bfloat162_rn(l0, l1);
    *(__nv_bfloat162*)(hi + off) = H;
    *(__nv_bfloat162*)(lo + off) = L;
}

// ---------------- fp32 [K,N] -> bf16 hi/lo [N,K] (transpose split) ----------------
__global__ void __launch_bounds__(256)
splitT_kernel(const float* __restrict__ in, __nv_bfloat16* __restrict__ hi,
              __nv_bfloat16* __restrict__ lo, int Kdim, int Ndim)
{
    __shared__ float t[32][33];
    const int n0 = blockIdx.x * 32, k0 = blockIdx.y * 32;
    const int tx = threadIdx.x & 31, ty = threadIdx.x >> 5;
#pragma unroll
    for (int j = 0; j < 4; j++) {
        int k = k0 + ty + j * 8;
        t[ty + j * 8][tx] = in[(size_t)k * Ndim + n0 + tx];
    }
    __syncthreads();
#pragma unroll
    for (int j = 0; j < 4; j++) {
        int n = n0 + ty + j * 8;
        float v = t[tx][ty + j * 8];
        __nv_bfloat16 h = __float2bfloat16(v);
        hi[(size_t)n * Kdim + k0 + tx] = h;
        lo[(size_t)n * Kdim + k0 + tx] = __float2bfloat16(v - __bfloat162float(h));
    }
}

// ---------------- split-bf16 tensor-core GEMM ----------------
// OMODE 0: Cf = acc + bias (+res), fp32.
// OMODE 1: (Ch,Cl) = split(relu?(acc + bias)), bf16 hi/lo.
#define PADK 40
#define TILE_B (128 * PADK * 2)
#define STAGE_B (4 * TILE_B)
#define GSMEM (2 * STAGE_B)

template <int OMODE>
__global__ void __launch_bounds__(256, 2)
mma_gemm(const __nv_bfloat16* __restrict__ Ah, const __nv_bfloat16* __restrict__ Al,
         const __nv_bfloat16* __restrict__ Bh, const __nv_bfloat16* __restrict__ Bl,
         const float* __restrict__ bias, const float* __restrict__ res,
         float* __restrict__ Cf, __nv_bfloat16* __restrict__ Ch,
         __nv_bfloat16* __restrict__ Cl,
         int M, int N, int K, int relu)
{
    extern __shared__ char smem[];
    const uint32_t sb = smem_u32(smem);

    const int tid = threadIdx.x, wid = tid >> 5, lane = tid & 31;
    const int bm = blockIdx.y * 128, bn = blockIdx.x * 128;
    const int wm = wid >> 2, wn = wid & 3;

    const __nv_bfloat16* srcs[4] = {
        Ah + (size_t)bm * K, Al + (size_t)bm * K,
        Bh + (size_t)bn * K, Bl + (size_t)bn * K };

    const int r0c = (tid * 2) >> 2, ch0 = (tid * 2) & 3;
    const int r1c = (tid * 2 + 1) >> 2, ch1 = (tid * 2 + 1) & 3;

    float d[4][4][4];
#pragma unroll
    for (int i = 0; i < 4; i++)
#pragma unroll
        for (int j = 0; j < 4; j++)
#pragma unroll
            for (int q = 0; q < 4; q++) d[i][j][q] = 0.f;

    const int NC = K >> 5;

    {
        const uint32_t st = sb;
#pragma unroll
        for (int t = 0; t < 4; t++) {
            cp16(st + t * TILE_B + r0c * 80 + ch0 * 16,
                 srcs[t] + (size_t)r0c * K + ch0 * 8);
            cp16(st + t * TILE_B + r1c * 80 + ch1 * 16,
                 srcs[t] + (size_t)r1c * K + ch1 * 8);
        }
        asm volatile("cp.async.commit_group;" ::: "memory");
    }

    for (int c = 0; c < NC; c++) {
        if (c + 1 < NC) {
            const int kc = (c + 1) << 5;
            const uint32_t st = sb + ((c + 1) & 1) * STAGE_B;
#pragma unroll
            for (int t = 0; t < 4; t++) {
                cp16(st + t * TILE_B + r0c * 80 + ch0 * 16,
                     srcs[t] + (size_t)r0c * K + kc + ch0 * 8);
                cp16(st + t * TILE_B + r1c * 80 + ch1 * 16,
                     srcs[t] + (size_t)r1c * K + kc + ch1 * 8);
            }
            asm volatile("cp.async.commit_group;" ::: "memory");
            asm volatile("cp.async.wait_group 1;" ::: "memory");
        } else {
            asm volatile("cp.async.wait_group 0;" ::: "memory");
        }
        __syncthreads();

        const uint32_t st = sb + (c & 1) * STAGE_B;
#pragma unroll
        for (int k16 = 0; k16 < 2; k16++) {
            const int koff = k16 * 16;
            uint32_t a_h[4][4], a_l[4][4], bfr[4][2];

            const uint32_t arow = (uint32_t)(wm * 64 + (lane & 15));
            const uint32_t acol = (uint32_t)((koff + 8 * (lane >> 4)) * 2);
#pragma unroll
            for (int i = 0; i < 4; i++) {
                uint32_t addr = st + (arow + i * 16) * 80 + acol;
                ldm_x4(addr, a_h[i]);
                ldm_x4(addr + TILE_B, a_l[i]);
            }

            const uint32_t bn_off = (uint32_t)(wn * 32 + (lane & 7) + 8 * ((lane >> 4) & 1));
            const uint32_t bk_off = (uint32_t)((koff + 8 * ((lane >> 3) & 1)) * 2);
#pragma unroll
            for (int nb = 0; nb < 2; nb++) {
                uint32_t r[4];
                uint32_t addr = st + 2 * TILE_B + (bn_off + nb * 16) * 80 + bk_off;
                ldm_x4(addr, r);
                bfr[nb * 2 + 0][0] = r[0]; bfr[nb * 2 + 0][1] = r[1];
                bfr[nb * 2 + 1][0] = r[2]; bfr[nb * 2 + 1][1] = r[3];
            }
#pragma unroll
            for (int i = 0; i < 4; i++)
#pragma unroll
                for (int j = 0; j < 4; j++) {
                    mma_bf16(d[i][j], a_h[i], bfr[j]);
                    mma_bf16(d[i][j], a_l[i], bfr[j]);
                }
#pragma unroll
            for (int nb = 0; nb < 2; nb++) {
                uint32_t r[4];
                uint32_t addr = st + 3 * TILE_B + (bn_off + nb * 16) * 80 + bk_off;
                ldm_x4(addr, r);
                bfr[nb * 2 + 0][0] = r[0]; bfr[nb * 2 + 0][1] = r[1];
                bfr[nb * 2 + 1][0] = r[2]; bfr[nb * 2 + 1][1] = r[3];
            }
#pragma unroll
            for (int i = 0; i < 4; i++)
#pragma unroll
                for (int j = 0; j < 4; j++)
                    mma_bf16(d[i][j], a_h[i], bfr[j]);
        }
        __syncthreads();
    }

    const int er = lane >> 2, ec = 2 * (lane & 3);
#pragma unroll
    for (int i = 0; i < 4; i++) {
#pragma unroll
        for (int rr = 0; rr < 2; rr++) {
            const int grow = bm + wm * 64 + i * 16 + er + rr * 8;
#pragma unroll
            for (int j = 0; j < 4; j++) {
                const int gcol = bn + wn * 32 + j * 8 + ec;
                float v0 = d[i][j][rr * 2 + 0] + bias[gcol];
                float v1 = d[i][j][rr * 2 + 1] + bias[gcol + 1];
                if (relu) { v0 = fmaxf(v0, 0.f); v1 = fmaxf(v1, 0.f); }
                if (OMODE == 0) {
                    if (res) {
                        v0 += res[(size_t)grow * N + gcol];
                        v1 += res[(size_t)grow * N + gcol + 1];
                    }
                    *(float2*)(Cf + (size_t)grow * N + gcol) = make_float2(v0, v1);
                } else {
                    split_store2(Ch, Cl, (size_t)grow * N + gcol, v0, v1);
                }
            }
        }
    }
}

// ---------------- LayerNorm -> bf16 hi/lo ----------------
__global__ void __launch_bounds__(256)
ln_bf16_kernel(const float* __restrict__ in, const float* __restrict__ gamma,
               const float* __restrict__ beta, __nv_bfloat16* __restrict__ hi,
               __nv_bfloat16* __restrict__ lo)
{
    const int row = blockIdx.x;
    const float* x = in + (size_t)row * DMODEL;
    const int tid = threadIdx.x;

    float4 v4 = *(const float4*)(x + tid * 4);
    float v[4] = {v4.x, v4.y, v4.z, v4.w};
    float s = 0.f, ss = 0.f;
#pragma unroll
    for (int j = 0; j < 4; j++) { s += v[j]; ss += v[j] * v[j]; }
#pragma unroll
    for (int o2 = 16; o2 > 0; o2 >>= 1) {
        s  += __shfl_xor_sync(0xffffffffu, s,  o2);
        ss += __shfl_xor_sync(0xffffffffu, ss, o2);
    }
    __shared__ float red[18];
    const int warp = tid >> 5, lane = tid & 31;
    if (lane == 0) { red[warp] = s; red[warp + 8] = ss; }
    __syncthreads();
    if (tid == 0) {
        float ts = 0.f, tss = 0.f;
#pragma unroll
        for (int w = 0; w < 8; w++) { ts += red[w]; tss += red[w + 8]; }
        float mu = ts / (float)DMODEL;
        float var = tss / (float)DMODEL - mu * mu;
        red[16] = mu;
        red[17] = rsqrtf(var + LN_EPS);
    }
    __syncthreads();
    const float mu = red[16], rstd = red[17];
    float y[4];
#pragma unroll
    for (int j = 0; j < 4; j++) {
        int idx = tid * 4 + j;
        y[j] = (v[j] - mu) * rstd * gamma[idx] + beta[idx];
    }
    split_store2(hi, lo, (size_t)row * DMODEL + tid * 4,     y[0], y[1]);
    split_store2(hi, lo, (size_t)row * DMODEL + tid * 4 + 2, y[2], y[3]);
}

// ---------------- Final LayerNorm (fp32 out) ----------------
__global__ void __launch_bounds__(256)
ln_kernel(const float* __restrict__ in, const float* __restrict__ gamma,
          const float* __restrict__ beta, float* __restrict__ out)
{
    const int row = blockIdx.x;
    const float* x = in + (size_t)row * DMODEL;
    float* o = out + (size_t)row * DMODEL;
    const int tid = threadIdx.x;

    float v[4];
    float s = 0.f, ss = 0.f;
#pragma unroll
    for (int j = 0; j < 4; j++) {
        v[j] = x[tid + j * 256];
        s += v[j];
        ss += v[j] * v[j];
    }
#pragma unroll
    for (int o2 = 16; o2 > 0; o2 >>= 1) {
        s  += __shfl_xor_sync(0xffffffffu, s,  o2);
        ss += __shfl_xor_sync(0xffffffffu, ss, o2);
    }
    __shared__ float red[18];
    const int warp = tid >> 5, lane = tid & 31;
    if (lane == 0) { red[warp] = s; red[warp + 8] = ss; }
    __syncthreads();
    if (tid == 0) {
        float ts = 0.f, tss = 0.f;
#pragma unroll
        for (int w = 0; w < 8; w++) { ts += red[w]; tss += red[w + 8]; }
        float mu = ts / (float)DMODEL;
        float var = tss / (float)DMODEL - mu * mu;
        red[16] = mu;
        red[17] = rsqrtf(var + LN_EPS);
    }
    __syncthreads();
    const float mu = red[16], rstd = red[17];
#pragma unroll
    for (int j = 0; j < 4; j++) {
        int idx = tid + j * 256;
        o[idx] = (v[j] - mu) * rstd * gamma[idx] + beta[idx];
    }
}

// ---------------- Flash attention, bf16 mma.sync ----------------
// Q-block 128 (warp w owns rows w*16..w*16+15), K-tiles of 64.
// Scores: split Q x split K (3 combos). PV: plain bf16 P x bf16 V.
#define FPAD 144                        // padded row bytes (72 bf16 elems)
#define S_QH 0
#define S_QL (128 * FPAD)               // 18432
#define S_KH (2 * 128 * FPAD)           // 36864
#define S_KL (S_KH + 64 * FPAD)         // 46080
#define S_VT (S_KL + 64 * FPAD)         // 55296
#define FLASH_SMEM (S_VT + 64 * FPAD)   // 64512

__global__ void __launch_bounds__(256, 2)
flash_mma(const __nv_bfloat16* __restrict__ qh, const __nv_bfloat16* __restrict__ ql,
          const __nv_bfloat16* __restrict__ kh, const __nv_bfloat16* __restrict__ kl,
          const __nv_bfloat16* __restrict__ vh,
          __nv_bfloat16* __restrict__ aoh, __nv_bfloat16* __restrict__ aol)
{
    extern __shared__ char smem[];
    const uint32_t sb = smem_u32(smem);

    const int qb = blockIdx.x, bh = blockIdx.y;
    const int b = bh >> 4, h = bh & 15;
    const int tid = threadIdx.x, wid = tid >> 5, lane = tid & 31;

    const size_t qrow0 = (size_t)b * SEQ + (size_t)qb * 128;
    const __nv_bfloat16* qhb = qh + qrow0 * DMODEL + h * 64;
    const __nv_bfloat16* qlb = ql + qrow0 * DMODEL + h * 64;
    const __nv_bfloat16* khb = kh + (size_t)b * SEQ * DMODEL + h * 64;
    const __nv_bfloat16* klb = kl + (size_t)b * SEQ * DMODEL + h * 64;
    const __nv_bfloat16* vhb = vh + (size_t)b * SEQ * DMODEL + h * 64;

    // stage Q (hi/lo) into smem: 128 rows x 64 cols, 8 x 16B chunks per row
#pragma unroll
    for (int it = 0; it < 4; it++) {
        int f = tid + it * 256;              // 0..1023
        int r = f >> 3, ch = f & 7;
        uint32_t dst = sb + r * FPAD + ch * 16;
        cp16(dst,          qhb + (size_t)r * DMODEL + ch * 8);
        cp16(dst + S_QL,   qlb + (size_t)r * DMODEL + ch * 8);
    }
    asm volatile("cp.async.commit_group;" ::: "memory");

    const float C = 0.125f * 1.44269504088896f;   // 1/sqrt(64) * log2(e)

    float o[8][4];
#pragma unroll
    for (int j = 0; j < 8; j++)
#pragma unroll
        for (int q = 0; q < 4; q++) o[j][q] = 0.f;
    float m0 = -INFINITY, m1 = -INFINITY, l0 = 0.f, l1 = 0.f;

    // per-thread fragment addressing constants
    const uint32_t aq_row = sb + (wid * 16 + (lane & 15)) * FPAD;
    const uint32_t acol_half = (uint32_t)(16 * (lane >> 4));          // bytes
    const uint32_t bn_row = (uint32_t)(((lane & 7) + 8 * ((lane >> 4) & 1)) * FPAD);
    const uint32_t bk_half = (uint32_t)(16 * ((lane >> 3) & 1));      // bytes

    const int vkv = tid >> 2, vdb = (tid & 3) * 16;
    __nv_bfloat16* vt = (__nv_bfloat16*)(smem + S_VT);

    for (int kt = 0; kt < SEQ / 64; kt++) {
        __syncthreads();   // previous tile's smem reads complete
        // load K hi/lo (cp.async) + V transposed (scalar)
#pragma unroll
        for (int it = 0; it < 2; it++) {
            int f = tid + it * 256;          // 0..511
            int r = f >> 3, ch = f & 7;
            uint32_t dst = sb + S_KH + r * FPAD + ch * 16;
            size_t go = (size_t)(kt * 64 + r) * DMODEL + ch * 8;
            cp16(dst, khb + go);
            cp16(dst + (S_KL - S_KH), klb + go);
        }
        {
            const __nv_bfloat16* vr = vhb + (size_t)(kt * 64 + vkv) * DMODEL + vdb;
            uint4 u0 = *(const uint4*)(vr);
            uint4 u1 = *(const uint4*)(vr + 8);
            const __nv_bfloat16* e0 = (const __nv_bfloat16*)&u0;
            const __nv_bfloat16* e1 = (const __nv_bfloat16*)&u1;
#pragma unroll
            for (int e = 0; e < 8; e++) {
                vt[(vdb + e) * 72 + vkv]     = e0[e];
                vt[(vdb + 8 + e) * 72 + vkv] = e1[e];
            }
        }
        asm volatile("cp.async.commit_group;" ::: "memory");
        asm volatile("cp.async.wait_group 0;" ::: "memory");
        __syncthreads();

        // ---- S = Q K^T (split x split, 3 combos) ----
        float s[8][4];
#pragma unroll
        for (int j = 0; j < 8; j++)
#pragma unroll
            for (int q = 0; q < 4; q++) s[j][q] = 0.f;

#pragma unroll
        for (int t = 0; t < 4; t++) {
            uint32_t ah[4], al[4];
            uint32_t aaddr = aq_row + t * 32 + acol_half;
            ldm_x4(aaddr, ah);
            ldm_x4(aaddr + S_QL, al);
            uint32_t kbase = sb + S_KH + bn_row + t * 32 + bk_half;
#pragma unroll
            for (int nb = 0; nb < 4; nb++) {
                uint32_t r[4];
                ldm_x4(kbase + nb * 16 * FPAD, r);
                mma_bf16(s[nb * 2],     ah, &r[0]);
                mma_bf16(s[nb * 2],     al, &r[0]);
                mma_bf16(s[nb * 2 + 1], ah, &r[2]);
                mma_bf16(s[nb * 2 + 1], al, &r[2]);
                ldm_x4(kbase + nb * 16 * FPAD + (S_KL - S_KH), r);
                mma_bf16(s[nb * 2],     ah, &r[0]);
                mma_bf16(s[nb * 2 + 1], ah, &r[2]);
            }
        }

        // ---- online softmax (base-2) ----
        float mx0 = -INFINITY, mx1 = -INFINITY;
#pragma unroll
        for (int j = 0; j < 8; j++) {
#pragma unroll
            for (int q = 0; q < 4; q++) s[j][q] *= C;
            mx0 = fmaxf(mx0, fmaxf(s[j][0], s[j][1]));
            mx1 = fmaxf(mx1, fmaxf(s[j][2], s[j][3]));
        }
        mx0 = fmaxf(mx0, __shfl_xor_sync(0xffffffffu, mx0, 1));
        mx0 = fmaxf(mx0, __shfl_xor_sync(0xffffffffu, mx0, 2));
        mx1 = fmaxf(mx1, __shfl_xor_sync(0xffffffffu, mx1, 1));
        mx1 = fmaxf(mx1, __shfl_xor_sync(0xffffffffu, mx1, 2));
        const float mn0 = fmaxf(m0, mx0), mn1 = fmaxf(m1, mx1);
        const float c0 = exp2f(m0 - mn0), c1 = exp2f(m1 - mn1);
        float rs0 = 0.f, rs1 = 0.f;
#pragma unroll
        for (int j = 0; j < 8; j++) {
            s[j][0] = exp2f(s[j][0] - mn0);
            s[j][1] = exp2f(s[j][1] - mn0);
            s[j][2] = exp2f(s[j][2] - mn1);
            s[j][3] = exp2f(s[j][3] - mn1);
            rs0 += s[j][0] + s[j][1];
            rs1 += s[j][2] + s[j][3];
        }
        rs0 += __shfl_xor_sync(0xffffffffu, rs0, 1);
        rs0 += __shfl_xor_sync(0xffffffffu, rs0, 2);
        rs1 += __shfl_xor_sync(0xffffffffu, rs1, 1);
        rs1 += __shfl_xor_sync(0xffffffffu, rs1, 2);
        l0 = l0 * c0 + rs0;
        l1 = l1 * c1 + rs1;
        m0 = mn0; m1 = mn1;
#pragma unroll
        for (int j = 0; j < 8; j++) {
            o[j][0] *= c0; o[j][1] *= c0;
            o[j][2] *= c1; o[j][3] *= c1;
        }

        // ---- O += P V ----
#pragma unroll
        for (int t = 0; t < 4; t++) {
            uint32_t pa[4];
            pa[0] = pack_bf2(s[2 * t][0],     s[2 * t][1]);
            pa[1] = pack_bf2(s[2 * t][2],     s[2 * t][3]);
            pa[2] = pack_bf2(s[2 * t + 1][0], s[2 * t + 1][1]);
            pa[3] = pack_bf2(s[2 * t + 1][2], s[2 * t + 1][3]);
            uint32_t vbase = sb + S_VT + bn_row + t * 32 + bk_half;
#pragma unroll
            for (int nb = 0; nb < 4; nb++) {
                uint32_t r[4];
                ldm_x4(vbase + nb * 16 * FPAD, r);
                mma_bf16(o[nb * 2],     pa, &r[0]);
                mma_bf16(o[nb * 2 + 1], pa, &r[2]);
            }
        }
    }

    // epilogue: normalize, split-store to ao hi/lo
    const float inv0 = 1.f / l0, inv1 = 1.f / l1;
    const size_t row0 = qrow0 + wid * 16 + (lane >> 2);
    const int colb = h * 64 + 2 * (lane & 3);
#pragma unroll
    for (int j = 0; j < 8; j++) {
        const size_t off0 = row0 * DMODEL + colb + j * 8;
        const size_t off1 = (row0 + 8) * DMODEL + colb + j * 8;
        split_store2(aoh, aol, off0, o[j][0] * inv0, o[j][1] * inv0);
        split_store2(aoh, aol, off1, o[j][2] * inv1, o[j][3] * inv1);
    }
}

// ---------------- host orchestration ----------------
extern "C" void kernel_launch(void* const* d_in, const int* in_sizes, int n_in,
                              void* d_out, int out_size)
{
    (void)in_sizes; (void)n_in; (void)out_size;
    const float* x    = (const float*)d_in[0];
    const float* Wq   = (const float*)d_in[1];
    const float* bq   = (const float*)d_in[2];
    const float* Wk   = (const float*)d_in[3];
    const float* bk   = (const float*)d_in[4];
    const float* Wv   = (const float*)d_in[5];
    const float* bv   = (const float*)d_in[6];
    const float* Wo   = (const float*)d_in[7];
    const float* bo   = (const float*)d_in[8];
    const float* W1   = (const float*)d_in[9];
    const float* b1   = (const float*)d_in[10];
    const float* W2   = (const float*)d_in[11];
    const float* b2   = (const float*)d_in[12];
    const float* gin  = (const float*)d_in[13];
    const float* bin  = (const float*)d_in[14];
    const float* gat  = (const float*)d_in[15];
    const float* bat  = (const float*)d_in[16];
    const float* gou  = (const float*)d_in[17];
    const float* bou  = (const float*)d_in[18];
    float* out = (float*)d_out;

    cudaFuncSetAttribute(mma_gemm<0>,
                         cudaFuncAttributeMaxDynamicSharedMemorySize, GSMEM);
    cudaFuncSetAttribute(mma_gemm<1>,
                         cudaFuncAttributeMaxDynamicSharedMemorySize, GSMEM);
    cudaFuncSetAttribute(flash_mma,
                         cudaFuncAttributeMaxDynamicSharedMemorySize, FLASH_SMEM);

    float *p_b0, *p_b1;
    __nv_bfloat16 *p_hh, *p_hl, *p_qh, *p_ql, *p_kh, *p_kl, *p_vh, *p_vl;
    __nv_bfloat16 *p_aoh, *p_aol, *p_ffh, *p_ffl, *p_wh, *p_wl;
    cudaGetSymbolAddress((void**)&p_b0,  g_buf0);
    cudaGetSymbolAddress((void**)&p_b1,  g_buf1);
    cudaGetSymbolAddress((void**)&p_hh,  g_hh);
    cudaGetSymbolAddress((void**)&p_hl,  g_hl);
    cudaGetSymbolAddress((void**)&p_qh,  g_qh);
    cudaGetSymbolAddress((void**)&p_ql,  g_ql);
    cudaGetSymbolAddress((void**)&p_kh,  g_kh);
    cudaGetSymbolAddress((void**)&p_kl,  g_kl);
    cudaGetSymbolAddress((void**)&p_vh,  g_vh);
    cudaGetSymbolAddress((void**)&p_vl,  g_vl);
    cudaGetSymbolAddress((void**)&p_aoh, g_aoh);
    cudaGetSymbolAddress((void**)&p_aol, g_aol);
    cudaGetSymbolAddress((void**)&p_ffh, g_ffh);
    cudaGetSymbolAddress((void**)&p_ffl, g_ffl);
    cudaGetSymbolAddress((void**)&p_wh,  g_wh);
    cudaGetSymbolAddress((void**)&p_wl,  g_wl);

    cudaMemcpyAsync(p_b0, x, (size_t)ROWS * DMODEL * sizeof(float),
                    cudaMemcpyDeviceToDevice);
    float* cur = p_b0;
    float* nxt = p_b1;

    const dim3 gD(DMODEL / 128, ROWS / 128);
    const dim3 gF(FF / 128, ROWS / 128);
    const dim3 gA(SEQ / 128, BH);
    const dim3 tD(DMODEL / 32, DMODEL / 32);
    const dim3 t1(FF / 32, DMODEL / 32);
    const dim3 t2(DMODEL / 32, FF / 32);

    for (int l = 0; l < LNUM; l++) {
        const float* wq = Wq + (size_t)l * DMODEL * DMODEL;
        const float* wk = Wk + (size_t)l * DMODEL * DMODEL;
        const float* wv = Wv + (size_t)l * DMODEL * DMODEL;
        const float* wo = Wo + (size_t)l * DMODEL * DMODEL;
        const float* w1 = W1 + (size_t)l * DMODEL * FF;
        const float* w2 = W2 + (size_t)l * FF * DMODEL;
        const float* vbq = bq + (size_t)l * DMODEL;
        const float* vbk = bk + (size_t)l * DMODEL;
        const float* vbv = bv + (size_t)l * DMODEL;
        const float* vbo = bo + (size_t)l * DMODEL;
        const float* vb1 = b1 + (size_t)l * FF;
        const float* vb2 = b2 + (size_t)l * DMODEL;

        // h = LN(out) -> bf16 hi/lo
        ln_bf16_kernel<<<ROWS, 256>>>(cur, gin, bin, p_hh, p_hl);

        // q/k/v projections -> bf16 hi/lo
        splitT_kernel<<<tD, 256>>>(wq, p_wh, p_wl, DMODEL, DMODEL);
        mma_gemm<1><<<gD, 256, GSMEM>>>(p_hh, p_hl, p_wh, p_wl, vbq, nullptr,
                                        nullptr, p_qh, p_ql, ROWS, DMODEL, DMODEL, 0);
        splitT_kernel<<<tD, 256>>>(wk, p_wh, p_wl, DMODEL, DMODEL);
        mma_gemm<1><<<gD, 256, GSMEM>>>(p_hh, p_hl, p_wh, p_wl, vbk, nullptr,
                                        nullptr, p_kh, p_kl, ROWS, DMODEL, DMODEL, 0);
        splitT_kernel<<<tD, 256>>>(wv, p_wh, p_wl, DMODEL, DMODEL);
        mma_gemm<1><<<gD, 256, GSMEM>>>(p_hh, p_hl, p_wh, p_wl, vbv, nullptr,
                                        nullptr, p_vh, p_vl, ROWS, DMODEL, DMODEL, 0);

        // fused attention (tensor cores) -> ao hi/lo
        flash_mma<<<gA, 256, FLASH_SMEM>>>(p_qh, p_ql, p_kh, p_kl, p_vh,
                                           p_aoh, p_aol);

        // out = out + ao @ Wo + bo (fp32)
        splitT_kernel<<<tD, 256>>>(wo, p_wh, p_wl, DMODEL, DMODEL);
        mma_gemm<0><<<gD, 256, GSMEM>>>(p_aoh, p_aol, p_wh, p_wl, vbo, cur,
                                        nxt, nullptr, nullptr, ROWS, DMODEL, DMODEL, 0);
        { float* t = cur; cur = nxt; nxt = t; }

        // FFN
        ln_bf16_kernel<<<ROWS, 256>>>(cur, gat, bat, p_hh, p_hl);
        splitT_kernel<<<t1, 256>>>(w1, p_wh, p_wl, DMODEL, FF);
        mma_gemm<1><<<gF, 256, GSMEM>>>(p_hh, p_hl, p_wh, p_wl, vb1, nullptr,
                                        nullptr, p_ffh, p_ffl, ROWS, FF, DMODEL, 1);
        splitT_kernel<<<t2, 256>>>(w2, p_wh, p_wl, FF, DMODEL);
        mma_gemm<0><<<gD, 256, GSMEM>>>(p_ffh, p_ffl, p_wh, p_wl, vb2, cur,
                                        nxt, nullptr, nullptr, ROWS, DMODEL, FF, 0);
        { float* t = cur; cur = nxt; nxt = t; }
    }

    ln_kernel<<<ROWS, 256>>>(cur, gou, bou, out);
}

// round 7
// speedup vs baseline: 5.2668x; 1.0355x over previous
#include <cuda_runtime.h>
#include <cuda_bf16.h>
#include <math.h>
#include <stdint.h>

// Problem constants
#define LNUM 2
#define HNUM 16
#define DMODEL 1024
#define FF 4096
#define BATCH 2
#define SEQ 2048
#define LN_EPS 1e-5f

#define ROWS (BATCH * SEQ)          // 4096
#define BH (BATCH * HNUM)           // 32
#define QKVN 3072

// ---------------- device scratch ----------------
__device__ float g_buf0[(size_t)ROWS * DMODEL];
__device__ float g_buf1[(size_t)ROWS * DMODEL];

__device__ __nv_bfloat16 g_hh  [(size_t)ROWS * DMODEL];
__device__ __nv_bfloat16 g_hl  [(size_t)ROWS * DMODEL];
__device__ __nv_bfloat16 g_qkvh[(size_t)ROWS * QKVN];
__device__ __nv_bfloat16 g_qkvl[(size_t)ROWS * QKVN];
__device__ __nv_bfloat16 g_aoh [(size_t)ROWS * DMODEL];
__device__ __nv_bfloat16 g_aol [(size_t)ROWS * DMODEL];
__device__ __nv_bfloat16 g_ffh [(size_t)ROWS * FF];
__device__ __nv_bfloat16 g_ffl [(size_t)ROWS * FF];
__device__ __nv_bfloat16 g_wh  [(size_t)FF * DMODEL];
__device__ __nv_bfloat16 g_wl  [(size_t)FF * DMODEL];

// ---------------- helpers ----------------
__device__ __forceinline__ uint32_t smem_u32(const void* p) {
    uint32_t a;
    asm("{ .reg .u64 t; cvta.to.shared.u64 t, %1; cvt.u32.u64 %0, t; }"
        : "=r"(a) : "l"(p));
    return a;
}

__device__ __forceinline__ void cp16(uint32_t dst, const void* src) {
    asm volatile("cp.async.cg.shared.global [%0], [%1], 16;"
                 :: "r"(dst), "l"(src));
}

__device__ __forceinline__ void ldm_x4(uint32_t addr, uint32_t r[4]) {
    asm volatile("ldmatrix.sync.aligned.m8n8.x4.shared.b16 {%0,%1,%2,%3}, [%4];"
                 : "=r"(r[0]), "=r"(r[1]), "=r"(r[2]), "=r"(r[3]) : "r"(addr));
}

__device__ __forceinline__ void ldm_x4_t(uint32_t addr, uint32_t r[4]) {
    asm volatile("ldmatrix.sync.aligned.m8n8.x4.trans.shared.b16 {%0,%1,%2,%3}, [%4];"
                 : "=r"(r[0]), "=r"(r[1]), "=r"(r[2]), "=r"(r[3]) : "r"(addr));
}

__device__ __forceinline__ void mma_bf16(float d[4], const uint32_t a[4],
                                         const uint32_t b[2]) {
    asm volatile(
        "mma.sync.aligned.m16n8k16.row.col.f32.bf16.bf16.f32 "
        "{%0,%1,%2,%3}, {%4,%5,%6,%7}, {%8,%9}, {%0,%1,%2,%3};"
        : "+f"(d[0]), "+f"(d[1]), "+f"(d[2]), "+f"(d[3])
        : "r"(a[0]), "r"(a[1]), "r"(a[2]), "r"(a[3]), "r"(b[0]), "r"(b[1]));
}

__device__ __forceinline__ uint32_t pack_bf2(float a, float b) {
    __nv_bfloat162 t = __floats2bfloat162_rn(a, b);
    return *(uint32_t*)&t;
}

__device__ __forceinline__ void split_store2(__nv_bfloat16* hi, __nv_bfloat16* lo,
                                             size_t off, float v0, float v1) {
    __nv_bfloat16 h0 = __float2bfloat16(v0), h1 = __float2bfloat16(v1);
    float l0 = v0 - __bfloat162float(h0), l1 = v1 - __bfloat162float(h1);
    __nv_bfloat162 H; H.x = h0; H.y = h1;
    __nv_bfloat162 L = __floats2bfloat162_rn(l0, l1);
    *(__nv_bfloat162*)(hi + off) = H;
    *(__nv_bfloat162*)(lo + off) = L;
}

#define CP_COMMIT() asm volatile("cp.async.commit_group;" ::: "memory")

// ---------------- fp32 [K,N] -> bf16 hi/lo [N,K] (transpose split) ----------------
__global__ void __launch_bounds__(256)
splitT_kernel(const float* __restrict__ in, __nv_bfloat16* __restrict__ hi,
              __nv_bfloat16* __restrict__ lo, int Kdim, int Ndim)
{
    __shared__ float t[32][33];
    const int n0 = blockIdx.x * 32, k0 = blockIdx.y * 32;
    const int tx = threadIdx.x & 31, ty = threadIdx.x >> 5;
#pragma unroll
    for (int j = 0; j < 4; j++) {
        int k = k0 + ty + j * 8;
        t[ty + j * 8][tx] = in[(size_t)k * Ndim + n0 + tx];
    }
    __syncthreads();
#pragma unroll
    for (int j = 0; j < 4; j++) {
        int n = n0 + ty + j * 8;
        float v = t[tx][ty + j * 8];
        __nv_bfloat16 h = __float2bfloat16(v);
        hi[(size_t)n * Kdim + k0 + tx] = h;
        lo[(size_t)n * Kdim + k0 + tx] = __float2bfloat16(v - __bfloat162float(h));
    }
}

// ---------------- split-bf16 tensor-core GEMM, 4-stage cp.async ring ----------------
// OMODE 0: Cf = acc + bias (+res), fp32.   OMODE 1: (Ch,Cl) = split(relu?(acc+bias)).
// K-chunks of 16; stage = 4 tiles (Ah,Al,Bh,Bl), each 128 rows x 16 elems, 48B rows.
#define TILE16 (128 * 48)              // 6144 B
#define STAGE16 (4 * TILE16)           // 24576 B
#define GSMEM (4 * STAGE16)            // 98304 B

template <int OMODE>
__global__ void __launch_bounds__(256, 2)
mma_gemm(const __nv_bfloat16* __restrict__ Ah, const __nv_bfloat16* __restrict__ Al,
         const __nv_bfloat16* __restrict__ Bh, const __nv_bfloat16* __restrict__ Bl,
         const float* __restrict__ bias0, const float* __restrict__ bias1,
         const float* __restrict__ bias2, int biasSeg,
         const float* __restrict__ res,
         float* __restrict__ Cf, __nv_bfloat16* __restrict__ Ch,
         __nv_bfloat16* __restrict__ Cl,
         int M, int N, int K, int relu)
{
    extern __shared__ char smem[];
    const uint32_t sb = smem_u32(smem);

    const int tid = threadIdx.x, wid = tid >> 5, lane = tid & 31;
    const int bm = blockIdx.y * 128, bn = blockIdx.x * 128;
    const int wm = wid >> 2, wn = wid & 3;

    const __nv_bfloat16* s0 = Ah + (size_t)bm * K;
    const __nv_bfloat16* s1 = Al + (size_t)bm * K;
    const __nv_bfloat16* s2 = Bh + (size_t)bn * K;
    const __nv_bfloat16* s3 = Bl + (size_t)bn * K;

    const int lr = tid >> 1, lc = tid & 1;        // loader: row, 16B-chunk
    const size_t lgo = (size_t)lr * K + lc * 8;   // per-tile global offset base
    const uint32_t lso = lr * 48 + lc * 16;       // smem offset within tile

    const int NC = K >> 4;

#define ISSUE_CHUNK(c)                                                     \
    do {                                                                   \
        const uint32_t st_ = sb + ((c) & 3) * STAGE16;                     \
        const int kc_ = (c) << 4;                                          \
        cp16(st_ + 0 * TILE16 + lso, s0 + lgo + kc_);                      \
        cp16(st_ + 1 * TILE16 + lso, s1 + lgo + kc_);                      \
        cp16(st_ + 2 * TILE16 + lso, s2 + lgo + kc_);                      \
        cp16(st_ + 3 * TILE16 + lso, s3 + lgo + kc_);                      \
        CP_COMMIT();                                                       \
    } while (0)

    ISSUE_CHUNK(0);
    ISSUE_CHUNK(1);
    ISSUE_CHUNK(2);

    float d[4][4][4];
#pragma unroll
    for (int i = 0; i < 4; i++)
#pragma unroll
        for (int j = 0; j < 4; j++)
#pragma unroll
            for (int q = 0; q < 4; q++) d[i][j][q] = 0.f;

    const uint32_t arow = (uint32_t)(wm * 64 + (lane & 15));
    const uint32_t abyte = (uint32_t)((lane >> 4) * 16);
    const uint32_t bnr = (uint32_t)(wn * 32 + (lane & 7) + 8 * ((lane >> 4) & 1));
    const uint32_t bkb = (uint32_t)(((lane >> 3) & 1) * 16);

    for (int c = 0; c < NC; c++) {
        if (c + 3 <= NC) {
            asm volatile("cp.async.wait_group 2;" ::: "memory");
        } else if (c + 2 == NC) {
            asm volatile("cp.async.wait_group 1;" ::: "memory");
        } else {
            asm volatile("cp.async.wait_group 0;" ::: "memory");
        }
        __syncthreads();
        if (c + 3 < NC) ISSUE_CHUNK(c + 3);

        const uint32_t st = sb + (c & 3) * STAGE16;
        uint32_t a_h[4][4], a_l[4][4], bfr[4][2];
#pragma unroll
        for (int i = 0; i < 4; i++) {
            uint32_t addr = st + (arow + i * 16) * 48 + abyte;
            ldm_x4(addr, a_h[i]);
            ldm_x4(addr + TILE16, a_l[i]);
        }
#pragma unroll
        for (int nb = 0; nb < 2; nb++) {
            uint32_t r[4];
            ldm_x4(st + 2 * TILE16 + (bnr + nb * 16) * 48 + bkb, r);
            bfr[nb * 2 + 0][0] = r[0]; bfr[nb * 2 + 0][1] = r[1];
            bfr[nb * 2 + 1][0] = r[2]; bfr[nb * 2 + 1][1] = r[3];
        }
#pragma unroll
        for (int i = 0; i < 4; i++)
#pragma unroll
            for (int j = 0; j < 4; j++) {
                mma_bf16(d[i][j], a_h[i], bfr[j]);
                mma_bf16(d[i][j], a_l[i], bfr[j]);
            }
#pragma unroll
        for (int nb = 0; nb < 2; nb++) {
            uint32_t r[4];
            ldm_x4(st + 3 * TILE16 + (bnr + nb * 16) * 48 + bkb, r);
            bfr[nb * 2 + 0][0] = r[0]; bfr[nb * 2 + 0][1] = r[1];
            bfr[nb * 2 + 1][0] = r[2]; bfr[nb * 2 + 1][1] = r[3];
        }
#pragma unroll
        for (int i = 0; i < 4; i++)
#pragma unroll
            for (int j = 0; j < 4; j++)
                mma_bf16(d[i][j], a_h[i], bfr[j]);
    }
#undef ISSUE_CHUNK

    // epilogue
    const int seg = bn / biasSeg;
    const float* bp = (seg == 0) ? bias0 : ((seg == 1) ? bias1 : bias2);
    const int bcol0 = bn - seg * biasSeg;
    const int er = lane >> 2, ec = 2 * (lane & 3);
#pragma unroll
    for (int i = 0; i < 4; i++) {
#pragma unroll
        for (int rr = 0; rr < 2; rr++) {
            const int grow = bm + wm * 64 + i * 16 + er + rr * 8;
#pragma unroll
            for (int j = 0; j < 4; j++) {
                const int coff = wn * 32 + j * 8 + ec;
                const int gcol = bn + coff;
                float v0 = d[i][j][rr * 2 + 0] + bp[bcol0 + coff];
                float v1 = d[i][j][rr * 2 + 1] + bp[bcol0 + coff + 1];
                if (relu) { v0 = fmaxf(v0, 0.f); v1 = fmaxf(v1, 0.f); }
                if (OMODE == 0) {
                    if (res) {
                        v0 += res[(size_t)grow * N + gcol];
                        v1 += res[(size_t)grow * N + gcol + 1];
                    }
                    *(float2*)(Cf + (size_t)grow * N + gcol) = make_float2(v0, v1);
                } else {
                    split_store2(Ch, Cl, (size_t)grow * N + gcol, v0, v1);
                }
            }
        }
    }
}

// ---------------- LayerNorm -> bf16 hi/lo ----------------
__global__ void __launch_bounds__(256)
ln_bf16_kernel(const float* __restrict__ in, const float* __restrict__ gamma,
               const float* __restrict__ beta, __nv_bfloat16* __restrict__ hi,
               __nv_bfloat16* __restrict__ lo)
{
    const int row = blockIdx.x;
    const float* x = in + (size_t)row * DMODEL;
    const int tid = threadIdx.x;

    float4 v4 = *(const float4*)(x + tid * 4);
    float v[4] = {v4.x, v4.y, v4.z, v4.w};
    float s = 0.f, ss = 0.f;
#pragma unroll
    for (int j = 0; j < 4; j++) { s += v[j]; ss += v[j] * v[j]; }
#pragma unroll
    for (int o2 = 16; o2 > 0; o2 >>= 1) {
        s  += __shfl_xor_sync(0xffffffffu, s,  o2);
        ss += __shfl_xor_sync(0xffffffffu, ss, o2);
    }
    __shared__ float red[18];
    const int warp = tid >> 5, lane = tid & 31;
    if (lane == 0) { red[warp] = s; red[warp + 8] = ss; }
    __syncthreads();
    if (tid == 0) {
        float ts = 0.f, tss = 0.f;
#pragma unroll
        for (int w = 0; w < 8; w++) { ts += red[w]; tss += red[w + 8]; }
        float mu = ts / (float)DMODEL;
        float var = tss / (float)DMODEL - mu * mu;
        red[16] = mu;
        red[17] = rsqrtf(var + LN_EPS);
    }
    __syncthreads();
    const float mu = red[16], rstd = red[17];
    float y[4];
#pragma unroll
    for (int j = 0; j < 4; j++) {
        int idx = tid * 4 + j;
        y[j] = (v[j] - mu) * rstd * gamma[idx] + beta[idx];
    }
    split_store2(hi, lo, (size_t)row * DMODEL + tid * 4,     y[0], y[1]);
    split_store2(hi, lo, (size_t)row * DMODEL + tid * 4 + 2, y[2], y[3]);
}

// ---------------- Final LayerNorm (fp32 out) ----------------
__global__ void __launch_bounds__(256)
ln_kernel(const float* __restrict__ in, const float* __restrict__ gamma,
          const float* __restrict__ beta, float* __restrict__ out)
{
    const int row = blockIdx.x;
    const float* x = in + (size_t)row * DMODEL;
    float* o = out + (size_t)row * DMODEL;
    const int tid = threadIdx.x;

    float v[4];
    float s = 0.f, ss = 0.f;
#pragma unroll
    for (int j = 0; j < 4; j++) {
        v[j] = x[tid + j * 256];
        s += v[j];
        ss += v[j] * v[j];
    }
#pragma unroll
    for (int o2 = 16; o2 > 0; o2 >>= 1) {
        s  += __shfl_xor_sync(0xffffffffu, s,  o2);
        ss += __shfl_xor_sync(0xffffffffu, ss, o2);
    }
    __shared__ float red[18];
    const int warp = tid >> 5, lane = tid & 31;
    if (lane == 0) { red[warp] = s; red[warp + 8] = ss; }
    __syncthreads();
    if (tid == 0) {
        float ts = 0.f, tss = 0.f;
#pragma unroll
        for (int w = 0; w < 8; w++) { ts += red[w]; tss += red[w + 8]; }
        float mu = ts / (float)DMODEL;
        float var = tss / (float)DMODEL - mu * mu;
        red[16] = mu;
        red[17] = rsqrtf(var + LN_EPS);
    }
    __syncthreads();
    const float mu = red[16], rstd = red[17];
#pragma unroll
    for (int j = 0; j < 4; j++) {
        int idx = tid + j * 256;
        o[idx] = (v[j] - mu) * rstd * gamma[idx] + beta[idx];
    }
}

// ---------------- Flash attention, bf16 mma.sync, double-buffered K/V ----------------
// Q from qkv[:, h*64], K from qkv[:, 1024+h*64], V from qkv[:, 2048+h*64].
// smem: Q hi (0) / Q lo (18432); stages at 36864 + s*27648: KH 0, KL 9216, V 18432.
#define F_SQL 18432
#define F_STG 36864
#define F_STGB 27648
#define FLASH_SMEM (F_STG + 2 * F_STGB)   // 92160

__global__ void __launch_bounds__(256, 2)
flash_mma(const __nv_bfloat16* __restrict__ qkvh,
          const __nv_bfloat16* __restrict__ qkvl,
          __nv_bfloat16* __restrict__ aoh, __nv_bfloat16* __restrict__ aol)
{
    extern __shared__ char smem[];
    const uint32_t sb = smem_u32(smem);

    const int qb = blockIdx.x, bh = blockIdx.y;
    const int b = bh >> 4, h = bh & 15;
    const int tid = threadIdx.x, wid = tid >> 5, lane = tid & 31;

    const size_t qrow0 = (size_t)b * SEQ + (size_t)qb * 128;
    const __nv_bfloat16* qhb = qkvh + qrow0 * QKVN + h * 64;
    const __nv_bfloat16* qlb = qkvl + qrow0 * QKVN + h * 64;
    const __nv_bfloat16* khb = qkvh + (size_t)b * SEQ * QKVN + 1024 + h * 64;
    const __nv_bfloat16* klb = qkvl + (size_t)b * SEQ * QKVN + 1024 + h * 64;
    const __nv_bfloat16* vhb = qkvh + (size_t)b * SEQ * QKVN + 2048 + h * 64;

    // G0: Q hi/lo + K/V stage 0
#pragma unroll
    for (int it = 0; it < 4; it++) {
        int f = tid + it * 256;
        int r = f >> 3, ch = f & 7;
        uint32_t dst = sb + r * 144 + ch * 16;
        size_t go = (size_t)r * QKVN + ch * 8;
        cp16(dst, qhb + go);
        cp16(dst + F_SQL, qlb + go);
    }
#pragma unroll
    for (int it = 0; it < 2; it++) {
        int f = tid + it * 256;
        int r = f >> 3, ch = f & 7;
        uint32_t dst = sb + F_STG + r * 144 + ch * 16;
        size_t go = (size_t)r * QKVN + ch * 8;
        cp16(dst, khb + go);
        cp16(dst + 9216, klb + go);
        cp16(dst + 18432, vhb + go);
    }
    CP_COMMIT();

    const float C = 0.125f * 1.44269504088896f;   // 1/sqrt(64) * log2(e)

    float o[8][4];
#pragma unroll
    for (int j = 0; j < 8; j++)
#pragma unroll
        for (int q = 0; q < 4; q++) o[j][q] = 0.f;
    float m0 = -INFINITY, m1 = -INFINITY, l0 = 0.f, l1 = 0.f;

    const uint32_t aq_row = sb + (wid * 16 + (lane & 15)) * 144;
    const uint32_t acol = (uint32_t)(16 * (lane >> 4));
    const uint32_t bn_row = (uint32_t)(((lane & 7) + 8 * ((lane >> 4) & 1)) * 144);
    const uint32_t bkb = (uint32_t)(16 * ((lane >> 3) & 1));
    const uint32_t v_row = (uint32_t)(((lane & 7) + 8 * ((lane >> 3) & 1)) * 144);
    const uint32_t v_db = (uint32_t)(16 * ((lane >> 4) & 1));

    for (int kt = 0; kt < SEQ / 64; kt++) {
        asm volatile("cp.async.wait_group 0;" ::: "memory");
        __syncthreads();

        if (kt + 1 < SEQ / 64) {
            uint32_t st = sb + F_STG + ((kt + 1) & 1) * F_STGB;
            size_t rbase = (size_t)(kt + 1) * 64;
#pragma unroll
            for (int it = 0; it < 2; it++) {
                int f = tid + it * 256;
                int r = f >> 3, ch = f & 7;
                uint32_t dst = st + r * 144 + ch * 16;
                size_t go = (rbase + r) * QKVN + ch * 8;
                cp16(dst, khb + go);
                cp16(dst + 9216, klb + go);
                cp16(dst + 18432, vhb + go);
            }
            CP_COMMIT();
        }

        const uint32_t kst = sb + F_STG + (kt & 1) * F_STGB;

        // ---- S = Q K^T (3 combos) ----
        float s[8][4];
#pragma unroll
        for (int j = 0; j < 8; j++)
#pragma unroll
            for (int q = 0; q < 4; q++) s[j][q] = 0.f;

#pragma unroll
        for (int t = 0; t < 4; t++) {
            uint32_t ah[4], al[4];
            uint32_t aaddr = aq_row + t * 32 + acol;
            ldm_x4(aaddr, ah);
            ldm_x4(aaddr + F_SQL, al);
            uint32_t kbase = kst + bn_row + t * 32 + bkb;
#pragma unroll
            for (int nb = 0; nb < 4; nb++) {
                uint32_t r[4];
                ldm_x4(kbase + nb * 16 * 144, r);
                mma_bf16(s[nb * 2],     ah, &r[0]);
                mma_bf16(s[nb * 2],     al, &r[0]);
                mma_bf16(s[nb * 2 + 1], ah, &r[2]);
                mma_bf16(s[nb * 2 + 1], al, &r[2]);
                ldm_x4(kbase + nb * 16 * 144 + 9216, r);
                mma_bf16(s[nb * 2],     ah, &r[0]);
                mma_bf16(s[nb * 2 + 1], ah, &r[2]);
            }
        }

        // ---- online softmax (base-2) ----
        float mx0 = -INFINITY, mx1 = -INFINITY;
#pragma unroll
        for (int j = 0; j < 8; j++) {
#pragma unroll
            for (int q = 0; q < 4; q++) s[j][q] *= C;
            mx0 = fmaxf(mx0, fmaxf(s[j][0], s[j][1]));
            mx1 = fmaxf(mx1, fmaxf(s[j][2], s[j][3]));
        }
        mx0 = fmaxf(mx0, __shfl_xor_sync(0xffffffffu, mx0, 1));
        mx0 = fmaxf(mx0, __shfl_xor_sync(0xffffffffu, mx0, 2));
        mx1 = fmaxf(mx1, __shfl_xor_sync(0xffffffffu, mx1, 1));
        mx1 = fmaxf(mx1, __shfl_xor_sync(0xffffffffu, mx1, 2));
        const float mn0 = fmaxf(m0, mx0), mn1 = fmaxf(m1, mx1);
        const float c0 = exp2f(m0 - mn0), c1 = exp2f(m1 - mn1);
        float rs0 = 0.f, rs1 = 0.f;
#pragma unroll
        for (int j = 0; j < 8; j++) {
            s[j][0] = exp2f(s[j][0] - mn0);
            s[j][1] = exp2f(s[j][1] - mn0);
            s[j][2] = exp2f(s[j][2] - mn1);
            s[j][3] = exp2f(s[j][3] - mn1);
            rs0 += s[j][0] + s[j][1];
            rs1 += s[j][2] + s[j][3];
        }
        rs0 += __shfl_xor_sync(0xffffffffu, rs0, 1);
        rs0 += __shfl_xor_sync(0xffffffffu, rs0, 2);
        rs1 += __shfl_xor_sync(0xffffffffu, rs1, 1);
        rs1 += __shfl_xor_sync(0xffffffffu, rs1, 2);
        l0 = l0 * c0 + rs0;
        l1 = l1 * c1 + rs1;
        m0 = mn0; m1 = mn1;
#pragma unroll
        for (int j = 0; j < 8; j++) {
            o[j][0] *= c0; o[j][1] *= c0;
            o[j][2] *= c1; o[j][3] *= c1;
        }

        // ---- O += P V (V fragments via ldmatrix.trans) ----
        const uint32_t vst = kst + 18432;
#pragma unroll
        for (int t = 0; t < 4; t++) {
            uint32_t pa[4];
            pa[0] = pack_bf2(s[2 * t][0],     s[2 * t][1]);
            pa[1] = pack_bf2(s[2 * t][2],     s[2 * t][3]);
            pa[2] = pack_bf2(s[2 * t + 1][0], s[2 * t + 1][1]);
            pa[3] = pack_bf2(s[2 * t + 1][2], s[2 * t + 1][3]);
            uint32_t vbase = vst + t * 16 * 144 + v_row + v_db;
#pragma unroll
            for (int nb = 0; nb < 4; nb++) {
                uint32_t r[4];
                ldm_x4_t(vbase + nb * 32, r);
                mma_bf16(o[nb * 2],     pa, &r[0]);
                mma_bf16(o[nb * 2 + 1], pa, &r[2]);
            }
        }
    }

    // epilogue: normalize, split-store to ao hi/lo
    const float inv0 = 1.f / l0, inv1 = 1.f / l1;
    const size_t row0 = qrow0 + wid * 16 + (lane >> 2);
    const int colb = h * 64 + 2 * (lane & 3);
#pragma unroll
    for (int j = 0; j < 8; j++) {
        const size_t off0 = row0 * DMODEL + colb + j * 8;
        const size_t off1 = (row0 + 8) * DMODEL + colb + j * 8;
        split_store2(aoh, aol, off0, o[j][0] * inv0, o[j][1] * inv0);
        split_store2(aoh, aol, off1, o[j][2] * inv1, o[j][3] * inv1);
    }
}

// ---------------- host orchestration ----------------
extern "C" void kernel_launch(void* const* d_in, const int* in_sizes, int n_in,
                              void* d_out, int out_size)
{
    (void)in_sizes; (void)n_in; (void)out_size;
    const float* x    = (const float*)d_in[0];
    const float* Wq   = (const float*)d_in[1];
    const float* bq   = (const float*)d_in[2];
    const float* Wk   = (const float*)d_in[3];
    const float* bk   = (const float*)d_in[4];
    const float* Wv   = (const float*)d_in[5];
    const float* bv   = (const float*)d_in[6];
    const float* Wo   = (const float*)d_in[7];
    const float* bo   = (const float*)d_in[8];
    const float* W1   = (const float*)d_in[9];
    const float* b1   = (const float*)d_in[10];
    const float* W2   = (const float*)d_in[11];
    const float* b2   = (const float*)d_in[12];
    const float* gin  = (const float*)d_in[13];
    const float* bin  = (const float*)d_in[14];
    const float* gat  = (const float*)d_in[15];
    const float* bat  = (const float*)d_in[16];
    const float* gou  = (const float*)d_in[17];
    const float* bou  = (const float*)d_in[18];
    float* out = (float*)d_out;

    cudaFuncSetAttribute(mma_gemm<0>,
                         cudaFuncAttributeMaxDynamicSharedMemorySize, GSMEM);
    cudaFuncSetAttribute(mma_gemm<1>,
                         cudaFuncAttributeMaxDynamicSharedMemorySize, GSMEM);
    cudaFuncSetAttribute(flash_mma,
                         cudaFuncAttributeMaxDynamicSharedMemorySize, FLASH_SMEM);

    float *p_b0, *p_b1;
    __nv_bfloat16 *p_hh, *p_hl, *p_qkvh, *p_qkvl;
    __nv_bfloat16 *p_aoh, *p_aol, *p_ffh, *p_ffl, *p_wh, *p_wl;
    cudaGetSymbolAddress((void**)&p_b0,   g_buf0);
    cudaGetSymbolAddress((void**)&p_b1,   g_buf1);
    cudaGetSymbolAddress((void**)&p_hh,   g_hh);
    cudaGetSymbolAddress((void**)&p_hl,   g_hl);
    cudaGetSymbolAddress((void**)&p_qkvh, g_qkvh);
    cudaGetSymbolAddress((void**)&p_qkvl, g_qkvl);
    cudaGetSymbolAddress((void**)&p_aoh,  g_aoh);
    cudaGetSymbolAddress((void**)&p_aol,  g_aol);
    cudaGetSymbolAddress((void**)&p_ffh,  g_ffh);
    cudaGetSymbolAddress((void**)&p_ffl,  g_ffl);
    cudaGetSymbolAddress((void**)&p_wh,   g_wh);
    cudaGetSymbolAddress((void**)&p_wl,   g_wl);

    cudaMemcpyAsync(p_b0, x, (size_t)ROWS * DMODEL * sizeof(float),
                    cudaMemcpyDeviceToDevice);
    float* cur = p_b0;
    float* nxt = p_b1;

    const dim3 gQKV(QKVN / 128, ROWS / 128);   // 24 x 32
    const dim3 gD(DMODEL / 128, ROWS / 128);   // 8 x 32
    const dim3 gF(FF / 128, ROWS / 128);       // 32 x 32
    const dim3 gA(SEQ / 128, BH);              // 16 x 32
    const dim3 tD(DMODEL / 32, DMODEL / 32);
    const dim3 t1(FF / 32, DMODEL / 32);
    const dim3 t2(DMODEL / 32, FF / 32);

    for (int l = 0; l < LNUM; l++) {
        const float* wq = Wq + (size_t)l * DMODEL * DMODEL;
        const float* wk = Wk + (size_t)l * DMODEL * DMODEL;
        const float* wv = Wv + (size_t)l * DMODEL * DMODEL;
        const float* wo = Wo + (size_t)l * DMODEL * DMODEL;
        const float* w1 = W1 + (size_t)l * DMODEL * FF;
        const float* w2 = W2 + (size_t)l * FF * DMODEL;
        const float* vbq = bq + (size_t)l * DMODEL;
        const float* vbk = bk + (size_t)l * DMODEL;
        const float* vbv = bv + (size_t)l * DMODEL;
        const float* vbo = bo + (size_t)l * DMODEL;
        const float* vb1 = b1 + (size_t)l * FF;
        const float* vb2 = b2 + (size_t)l * DMODEL;

        // h = LN(out) -> bf16 hi/lo
        ln_bf16_kernel<<<ROWS, 256>>>(cur, gin, bin, p_hh, p_hl);

        // QKV fused: weights transposed into one [3072,1024] buffer
        splitT_kernel<<<tD, 256>>>(wq, p_wh, p_wl, DMODEL, DMODEL);
        splitT_kernel<<<tD, 256>>>(wk, p_wh + (size_t)DMODEL * DMODEL,
                                   p_wl + (size_t)DMODEL * DMODEL, DMODEL, DMODEL);
        splitT_kernel<<<tD, 256>>>(wv, p_wh + 2 * (size_t)DMODEL * DMODEL,
                                   p_wl + 2 * (size_t)DMODEL * DMODEL, DMODEL, DMODEL);
        mma_gemm<1><<<gQKV, 256, GSMEM>>>(p_hh, p_hl, p_wh, p_wl,
                                          vbq, vbk, vbv, DMODEL, nullptr,
                                          nullptr, p_qkvh, p_qkvl,
                                          ROWS, QKVN, DMODEL, 0);

        // fused attention -> ao hi/lo
        flash_mma<<<gA, 256, FLASH_SMEM>>>(p_qkvh, p_qkvl, p_aoh, p_aol);

        // out = out + ao @ Wo + bo (fp32)
        splitT_kernel<<<tD, 256>>>(wo, p_wh, p_wl, DMODEL, DMODEL);
        mma_gemm<0><<<gD, 256, GSMEM>>>(p_aoh, p_aol, p_wh, p_wl,
                                        vbo, vbo, vbo, DMODEL, cur,
                                        nxt, nullptr, nullptr,
                                        ROWS, DMODEL, DMODEL, 0);
        { float* t = cur; cur = nxt; nxt = t; }

        // FFN
        ln_bf16_kernel<<<ROWS, 256>>>(cur, gat, bat, p_hh, p_hl);
        splitT_kernel<<<t1, 256>>>(w1, p_wh, p_wl, DMODEL, FF);
        mma_gemm<1><<<gF, 256, GSMEM>>>(p_hh, p_hl, p_wh, p_wl,
                                        vb1, vb1, vb1, FF, nullptr,
                                        nullptr, p_ffh, p_ffl,
                                        ROWS, FF, DMODEL, 1);
        splitT_kernel<<<t2, 256>>>(w2, p_wh, p_wl, FF, DMODEL);
        mma_gemm<0><<<gD, 256, GSMEM>>>(p_ffh, p_ffl, p_wh, p_wl,
                                        vb2, vb2, vb2, DMODEL, cur,
                                        nxt, nullptr, nullptr,
                                        ROWS, DMODEL, FF, 0);
        { float* t = cur; cur = nxt; nxt = t; }
    }

    ln_kernel<<<ROWS, 256>>>(cur, gou, bou, out);
}

// round 8
// speedup vs baseline: 11.4844x; 2.1806x over previous
#include <cuda_runtime.h>
#include <cuda_fp16.h>
#include <math.h>
#include <stdint.h>

// Problem constants
#define LNUM 2
#define HNUM 16
#define DMODEL 1024
#define FF 4096
#define BATCH 2
#define SEQ 2048
#define LN_EPS 1e-5f

#define ROWS (BATCH * SEQ)          // 4096
#define BH (BATCH * HNUM)           // 32
#define QKVN 3072

// ---------------- device scratch ----------------
__device__ float g_buf0[(size_t)ROWS * DMODEL];
__device__ float g_buf1[(size_t)ROWS * DMODEL];

__device__ __half g_h  [(size_t)ROWS * DMODEL];
__device__ __half g_qkv[(size_t)ROWS * QKVN];
__device__ __half g_ao [(size_t)ROWS * DMODEL];
__device__ __half g_ff [(size_t)ROWS * FF];
__device__ __half g_w  [(size_t)FF * DMODEL];

// ---------------- helpers ----------------
__device__ __forceinline__ uint32_t smem_u32(const void* p) {
    uint32_t a;
    asm("{ .reg .u64 t; cvta.to.shared.u64 t, %1; cvt.u32.u64 %0, t; }"
        : "=r"(a) : "l"(p));
    return a;
}

__device__ __forceinline__ void cp16(uint32_t dst, const void* src) {
    asm volatile("cp.async.cg.shared.global [%0], [%1], 16;"
                 :: "r"(dst), "l"(src));
}

__device__ __forceinline__ void ldm_x4(uint32_t addr, uint32_t r[4]) {
    asm volatile("ldmatrix.sync.aligned.m8n8.x4.shared.b16 {%0,%1,%2,%3}, [%4];"
                 : "=r"(r[0]), "=r"(r[1]), "=r"(r[2]), "=r"(r[3]) : "r"(addr));
}

__device__ __forceinline__ void ldm_x4_t(uint32_t addr, uint32_t r[4]) {
    asm volatile("ldmatrix.sync.aligned.m8n8.x4.trans.shared.b16 {%0,%1,%2,%3}, [%4];"
                 : "=r"(r[0]), "=r"(r[1]), "=r"(r[2]), "=r"(r[3]) : "r"(addr));
}

__device__ __forceinline__ void mma_f16(float d[4], const uint32_t a[4],
                                        const uint32_t b[2]) {
    asm volatile(
        "mma.sync.aligned.m16n8k16.row.col.f32.f16.f16.f32 "
        "{%0,%1,%2,%3}, {%4,%5,%6,%7}, {%8,%9}, {%0,%1,%2,%3};"
        : "+f"(d[0]), "+f"(d[1]), "+f"(d[2]), "+f"(d[3])
        : "r"(a[0]), "r"(a[1]), "r"(a[2]), "r"(a[3]), "r"(b[0]), "r"(b[1]));
}

__device__ __forceinline__ uint32_t pack_h2(float a, float b) {
    __half2 t = __floats2half2_rn(a, b);
    return *(uint32_t*)&t;
}

__device__ __forceinline__ void hstore2(__half* p, size_t off, float v0, float v1) {
    *(__half2*)(p + off) = __floats2half2_rn(v0, v1);
}

#define CP_COMMIT() asm volatile("cp.async.commit_group;" ::: "memory")

// ---------------- fp32 [K,N] -> fp16 [N,K] (transpose cast) ----------------
__global__ void __launch_bounds__(256)
castT_kernel(const float* __restrict__ in, __half* __restrict__ outT,
             int Kdim, int Ndim)
{
    __shared__ float t[32][33];
    const int n0 = blockIdx.x * 32, k0 = blockIdx.y * 32;
    const int tx = threadIdx.x & 31, ty = threadIdx.x >> 5;
#pragma unroll
    for (int j = 0; j < 4; j++) {
        int k = k0 + ty + j * 8;
        t[ty + j * 8][tx] = in[(size_t)k * Ndim + n0 + tx];
    }
    __syncthreads();
#pragma unroll
    for (int j = 0; j < 4; j++) {
        int n = n0 + ty + j * 8;
        outT[(size_t)n * Kdim + k0 + tx] = __float2half(t[tx][ty + j * 8]);
    }
}

// ---------------- fp16 tensor-core GEMM, 4-stage cp.async ring, K-chunk 32 ----------------
// OMODE 0: Cf = acc + bias (+res), fp32.   OMODE 1: Ch = fp16(relu?(acc+bias)).
// A: [M,K] fp16 row-major. B: [N,K] fp16 row-major. 128x128 tile.
#define TILEB (128 * 80)               // 10240 B (32 fp16 cols + 16B pad per row)
#define STAGEB (2 * TILEB)             // 20480 B
#define GSMEM (4 * STAGEB)             // 81920 B

template <int OMODE>
__global__ void __launch_bounds__(256, 2)
mma_gemm(const __half* __restrict__ A, const __half* __restrict__ B,
         const float* __restrict__ bias0, const float* __restrict__ bias1,
         const float* __restrict__ bias2, int biasSeg,
         const float* __restrict__ res,
         float* __restrict__ Cf, __half* __restrict__ Ch,
         int M, int N, int K, int relu)
{
    extern __shared__ char smem[];
    const uint32_t sb = smem_u32(smem);

    const int tid = threadIdx.x, wid = tid >> 5, lane = tid & 31;
    const int bm = blockIdx.y * 128, bn = blockIdx.x * 128;
    const int wm = wid >> 2, wn = wid & 3;     // warp tile 64 x 32

    const __half* sA = A + (size_t)bm * K;
    const __half* sB = B + (size_t)bn * K;

    // loader: 2 chunks/thread/tile. idx = tid*2+j : row = idx>>2, 16B-chunk = idx&3
    const int r0 = (tid * 2) >> 2, c0 = (tid * 2) & 3;
    const int r1 = (tid * 2 + 1) >> 2, c1 = (tid * 2 + 1) & 3;

    const int NC = K >> 5;

#define ISSUE_CHUNK(c)                                                      \
    do {                                                                    \
        const uint32_t st_ = sb + ((c) & 3) * STAGEB;                       \
        const int kc_ = (c) << 5;                                           \
        cp16(st_ + r0 * 80 + c0 * 16, sA + (size_t)r0 * K + kc_ + c0 * 8);  \
        cp16(st_ + r1 * 80 + c1 * 16, sA + (size_t)r1 * K + kc_ + c1 * 8);  \
        cp16(st_ + TILEB + r0 * 80 + c0 * 16,                               \
             sB + (size_t)r0 * K + kc_ + c0 * 8);                           \
        cp16(st_ + TILEB + r1 * 80 + c1 * 16,                               \
             sB + (size_t)r1 * K + kc_ + c1 * 8);                           \
        CP_COMMIT();                                                        \
    } while (0)

    ISSUE_CHUNK(0);
    ISSUE_CHUNK(1);
    ISSUE_CHUNK(2);

    float d[4][4][4];
#pragma unroll
    for (int i = 0; i < 4; i++)
#pragma unroll
        for (int j = 0; j < 4; j++)
#pragma unroll
            for (int q = 0; q < 4; q++) d[i][j][q] = 0.f;

    const uint32_t arow = (uint32_t)(wm * 64 + (lane & 15));
    const uint32_t abyte = (uint32_t)((lane >> 4) * 16);
    const uint32_t bnr = (uint32_t)(wn * 32 + (lane & 7) + 8 * ((lane >> 4) & 1));
    const uint32_t bkb = (uint32_t)(((lane >> 3) & 1) * 16);

    for (int c = 0; c < NC; c++) {
        if (c + 3 <= NC) {
            asm volatile("cp.async.wait_group 2;" ::: "memory");
        } else if (c + 2 == NC) {
            asm volatile("cp.async.wait_group 1;" ::: "memory");
        } else {
            asm volatile("cp.async.wait_group 0;" ::: "memory");
        }
        __syncthreads();
        if (c + 3 < NC) ISSUE_CHUNK(c + 3);

        const uint32_t st = sb + (c & 3) * STAGEB;
#pragma unroll
        for (int k16 = 0; k16 < 2; k16++) {
            uint32_t af[4][4], bfr[4][2];
#pragma unroll
            for (int i = 0; i < 4; i++)
                ldm_x4(st + (arow + i * 16) * 80 + k16 * 32 + abyte, af[i]);
#pragma unroll
            for (int nb = 0; nb < 2; nb++) {
                uint32_t r[4];
                ldm_x4(st + TILEB + (bnr + nb * 16) * 80 + k16 * 32 + bkb, r);
                bfr[nb * 2 + 0][0] = r[0]; bfr[nb * 2 + 0][1] = r[1];
                bfr[nb * 2 + 1][0] = r[2]; bfr[nb * 2 + 1][1] = r[3];
            }
#pragma unroll
            for (int i = 0; i < 4; i++)
#pragma unroll
                for (int j = 0; j < 4; j++)
                    mma_f16(d[i][j], af[i], bfr[j]);
        }
    }
#undef ISSUE_CHUNK

    // epilogue
    const int seg = bn / biasSeg;
    const float* bp = (seg == 0) ? bias0 : ((seg == 1) ? bias1 : bias2);
    const int bcol0 = bn - seg * biasSeg;
    const int er = lane >> 2, ec = 2 * (lane & 3);
#pragma unroll
    for (int i = 0; i < 4; i++) {
#pragma unroll
        for (int rr = 0; rr < 2; rr++) {
            const int grow = bm + wm * 64 + i * 16 + er + rr * 8;
#pragma unroll
            for (int j = 0; j < 4; j++) {
                const int coff = wn * 32 + j * 8 + ec;
                const int gcol = bn + coff;
                float v0 = d[i][j][rr * 2 + 0] + bp[bcol0 + coff];
                float v1 = d[i][j][rr * 2 + 1] + bp[bcol0 + coff + 1];
                if (relu) { v0 = fmaxf(v0, 0.f); v1 = fmaxf(v1, 0.f); }
                if (OMODE == 0) {
                    if (res) {
                        v0 += res[(size_t)grow * N + gcol];
                        v1 += res[(size_t)grow * N + gcol + 1];
                    }
                    *(float2*)(Cf + (size_t)grow * N + gcol) = make_float2(v0, v1);
                } else {
                    hstore2(Ch, (size_t)grow * N + gcol, v0, v1);
                }
            }
        }
    }
}

// ---------------- LayerNorm -> fp16 ----------------
__global__ void __launch_bounds__(256)
ln_h_kernel(const float* __restrict__ in, const float* __restrict__ gamma,
            const float* __restrict__ beta, __half* __restrict__ out)
{
    const int row = blockIdx.x;
    const float* x = in + (size_t)row * DMODEL;
    const int tid = threadIdx.x;

    float4 v4 = *(const float4*)(x + tid * 4);
    float v[4] = {v4.x, v4.y, v4.z, v4.w};
    float s = 0.f, ss = 0.f;
#pragma unroll
    for (int j = 0; j < 4; j++) { s += v[j]; ss += v[j] * v[j]; }
#pragma unroll
    for (int o2 = 16; o2 > 0; o2 >>= 1) {
        s  += __shfl_xor_sync(0xffffffffu, s,  o2);
        ss += __shfl_xor_sync(0xffffffffu, ss, o2);
    }
    __shared__ float red[18];
    const int warp = tid >> 5, lane = tid & 31;
    if (lane == 0) { red[warp] = s; red[warp + 8] = ss; }
    __syncthreads();
    if (tid == 0) {
        float ts = 0.f, tss = 0.f;
#pragma unroll
        for (int w = 0; w < 8; w++) { ts += red[w]; tss += red[w + 8]; }
        float mu = ts / (float)DMODEL;
        float var = tss / (float)DMODEL - mu * mu;
        red[16] = mu;
        red[17] = rsqrtf(var + LN_EPS);
    }
    __syncthreads();
    const float mu = red[16], rstd = red[17];
    float y[4];
#pragma unroll
    for (int j = 0; j < 4; j++) {
        int idx = tid * 4 + j;
        y[j] = (v[j] - mu) * rstd * gamma[idx] + beta[idx];
    }
    hstore2(out, (size_t)row * DMODEL + tid * 4,     y[0], y[1]);
    hstore2(out, (size_t)row * DMODEL + tid * 4 + 2, y[2], y[3]);
}

// ---------------- Final LayerNorm (fp32 out) ----------------
__global__ void __launch_bounds__(256)
ln_kernel(const float* __restrict__ in, const float* __restrict__ gamma,
          const float* __restrict__ beta, float* __restrict__ out)
{
    const int row = blockIdx.x;
    const float* x = in + (size_t)row * DMODEL;
    float* o = out + (size_t)row * DMODEL;
    const int tid = threadIdx.x;

    float v[4];
    float s = 0.f, ss = 0.f;
#pragma unroll
    for (int j = 0; j < 4; j++) {
        v[j] = x[tid + j * 256];
        s += v[j];
        ss += v[j] * v[j];
    }
#pragma unroll
    for (int o2 = 16; o2 > 0; o2 >>= 1) {
        s  += __shfl_xor_sync(0xffffffffu, s,  o2);
        ss += __shfl_xor_sync(0xffffffffu, ss, o2);
    }
    __shared__ float red[18];
    const int warp = tid >> 5, lane = tid & 31;
    if (lane == 0) { red[warp] = s; red[warp + 8] = ss; }
    __syncthreads();
    if (tid == 0) {
        float ts = 0.f, tss = 0.f;
#pragma unroll
        for (int w = 0; w < 8; w++) { ts += red[w]; tss += red[w + 8]; }
        float mu = ts / (float)DMODEL;
        float var = tss / (float)DMODEL - mu * mu;
        red[16] = mu;
        red[17] = rsqrtf(var + LN_EPS);
    }
    __syncthreads();
    const float mu = red[16], rstd = red[17];
#pragma unroll
    for (int j = 0; j < 4; j++) {
        int idx = tid + j * 256;
        o[idx] = (v[j] - mu) * rstd * gamma[idx] + beta[idx];
    }
}

// ---------------- Flash attention, fp16 mma.sync, double-buffered K/V ----------------
// Q from qkv[:, h*64], K from qkv[:, 1024+h*64], V from qkv[:, 2048+h*64].
// smem: Q (0, 18432B); stage s at 18432 + s*18432: K +0 (9216), V +9216.
#define F_STG 18432
#define F_STGB 18432
#define FLASH_SMEM (F_STG + 2 * F_STGB)   // 55296

__global__ void __launch_bounds__(256, 2)
flash_mma(const __half* __restrict__ qkv, __half* __restrict__ ao)
{
    extern __shared__ char smem[];
    const uint32_t sb = smem_u32(smem);

    const int qb = blockIdx.x, bh = blockIdx.y;
    const int b = bh >> 4, h = bh & 15;
    const int tid = threadIdx.x, wid = tid >> 5, lane = tid & 31;

    const size_t qrow0 = (size_t)b * SEQ + (size_t)qb * 128;
    const __half* qp = qkv + qrow0 * QKVN + h * 64;
    const __half* kp = qkv + (size_t)b * SEQ * QKVN + 1024 + h * 64;
    const __half* vp = qkv + (size_t)b * SEQ * QKVN + 2048 + h * 64;

    // stage Q + K/V tile 0
#pragma unroll
    for (int it = 0; it < 4; it++) {
        int f = tid + it * 256;
        int r = f >> 3, ch = f & 7;
        cp16(sb + r * 144 + ch * 16, qp + (size_t)r * QKVN + ch * 8);
    }
#pragma unroll
    for (int it = 0; it < 2; it++) {
        int f = tid + it * 256;
        int r = f >> 3, ch = f & 7;
        uint32_t dst = sb + F_STG + r * 144 + ch * 16;
        size_t go = (size_t)r * QKVN + ch * 8;
        cp16(dst, kp + go);
        cp16(dst + 9216, vp + go);
    }
    CP_COMMIT();

    const float C = 0.125f * 1.44269504088896f;   // 1/sqrt(64) * log2(e)

    float o[8][4];
#pragma unroll
    for (int j = 0; j < 8; j++)
#pragma unroll
        for (int q = 0; q < 4; q++) o[j][q] = 0.f;
    float m0 = -INFINITY, m1 = -INFINITY, l0 = 0.f, l1 = 0.f;

    const uint32_t aq_row = sb + (wid * 16 + (lane & 15)) * 144;
    const uint32_t acol = (uint32_t)(16 * (lane >> 4));
    const uint32_t bn_row = (uint32_t)(((lane & 7) + 8 * ((lane >> 4) & 1)) * 144);
    const uint32_t bkb = (uint32_t)(16 * ((lane >> 3) & 1));
    const uint32_t v_row = (uint32_t)(((lane & 7) + 8 * ((lane >> 3) & 1)) * 144);
    const uint32_t v_db = (uint32_t)(16 * ((lane >> 4) & 1));

    for (int kt = 0; kt < SEQ / 64; kt++) {
        asm volatile("cp.async.wait_group 0;" ::: "memory");
        __syncthreads();

        if (kt + 1 < SEQ / 64) {
            uint32_t st = sb + F_STG + ((kt + 1) & 1) * F_STGB;
            size_t rbase = (size_t)(kt + 1) * 64;
#pragma unroll
            for (int it = 0; it < 2; it++) {
                int f = tid + it * 256;
                int r = f >> 3, ch = f & 7;
                uint32_t dst = st + r * 144 + ch * 16;
                size_t go = (rbase + r) * QKVN + ch * 8;
                cp16(dst, kp + go);
                cp16(dst + 9216, vp + go);
            }
            CP_COMMIT();
        }

        const uint32_t kst = sb + F_STG + (kt & 1) * F_STGB;

        // ---- S = Q K^T ----
        float s[8][4];
#pragma unroll
        for (int j = 0; j < 8; j++)
#pragma unroll
            for (int q = 0; q < 4; q++) s[j][q] = 0.f;

#pragma unroll
        for (int t = 0; t < 4; t++) {
            uint32_t af[4];
            ldm_x4(aq_row + t * 32 + acol, af);
            uint32_t kbase = kst + bn_row + t * 32 + bkb;
#pragma unroll
            for (int nb = 0; nb < 4; nb++) {
                uint32_t r[4];
                ldm_x4(kbase + nb * 16 * 144, r);
                mma_f16(s[nb * 2],     af, &r[0]);
                mma_f16(s[nb * 2 + 1], af, &r[2]);
            }
        }

        // ---- online softmax (base-2) ----
        float mx0 = -INFINITY, mx1 = -INFINITY;
#pragma unroll
        for (int j = 0; j < 8; j++) {
#pragma unroll
            for (int q = 0; q < 4; q++) s[j][q] *= C;
            mx0 = fmaxf(mx0, fmaxf(s[j][0], s[j][1]));
            mx1 = fmaxf(mx1, fmaxf(s[j][2], s[j][3]));
        }
        mx0 = fmaxf(mx0, __shfl_xor_sync(0xffffffffu, mx0, 1));
        mx0 = fmaxf(mx0, __shfl_xor_sync(0xffffffffu, mx0, 2));
        mx1 = fmaxf(mx1, __shfl_xor_sync(0xffffffffu, mx1, 1));
        mx1 = fmaxf(mx1, __shfl_xor_sync(0xffffffffu, mx1, 2));
        const float mn0 = fmaxf(m0, mx0), mn1 = fmaxf(m1, mx1);
        const float c0 = exp2f(m0 - mn0), c1 = exp2f(m1 - mn1);
        float rs0 = 0.f, rs1 = 0.f;
#pragma unroll
        for (int j = 0; j < 8; j++) {
            s[j][0] = exp2f(s[j][0] - mn0);
            s[j][1] = exp2f(s[j][1] - mn0);
            s[j][2] = exp2f(s[j][2] - mn1);
            s[j][3] = exp2f(s[j][3] - mn1);
            rs0 += s[j][0] + s[j][1];
            rs1 += s[j][2] + s[j][3];
        }
        rs0 += __shfl_xor_sync(0xffffffffu, rs0, 1);
        rs0 += __shfl_xor_sync(0xffffffffu, rs0, 2);
        rs1 += __shfl_xor_sync(0xffffffffu, rs1, 1);
        rs1 += __shfl_xor_sync(0xffffffffu, rs1, 2);
        l0 = l0 * c0 + rs0;
        l1 = l1 * c1 + rs1;
        m0 = mn0; m1 = mn1;
#pragma unroll
        for (int j = 0; j < 8; j++) {
            o[j][0] *= c0; o[j][1] *= c0;
            o[j][2] *= c1; o[j][3] *= c1;
        }

        // ---- O += P V (V fragments via ldmatrix.trans) ----
        const uint32_t vst = kst + 9216;
#pragma unroll
        for (int t = 0; t < 4; t++) {
            uint32_t pa[4];
            pa[0] = pack_h2(s[2 * t][0],     s[2 * t][1]);
            pa[1] = pack_h2(s[2 * t][2],     s[2 * t][3]);
            pa[2] = pack_h2(s[2 * t + 1][0], s[2 * t + 1][1]);
            pa[3] = pack_h2(s[2 * t + 1][2], s[2 * t + 1][3]);
            uint32_t vbase = vst + t * 16 * 144 + v_row + v_db;
#pragma unroll
            for (int nb = 0; nb < 4; nb++) {
                uint32_t r[4];
                ldm_x4_t(vbase + nb * 32, r);
                mma_f16(o[nb * 2],     pa, &r[0]);
                mma_f16(o[nb * 2 + 1], pa, &r[2]);
            }
        }
    }

    // epilogue: normalize, store fp16
    const float inv0 = 1.f / l0, inv1 = 1.f / l1;
    const size_t row0 = qrow0 + wid * 16 + (lane >> 2);
    const int colb = h * 64 + 2 * (lane & 3);
#pragma unroll
    for (int j = 0; j < 8; j++) {
        hstore2(ao, row0 * DMODEL + colb + j * 8,       o[j][0] * inv0, o[j][1] * inv0);
        hstore2(ao, (row0 + 8) * DMODEL + colb + j * 8, o[j][2] * inv1, o[j][3] * inv1);
    }
}

// ---------------- host orchestration ----------------
extern "C" void kernel_launch(void* const* d_in, const int* in_sizes, int n_in,
                              void* d_out, int out_size)
{
    (void)in_sizes; (void)n_in; (void)out_size;
    const float* x    = (const float*)d_in[0];
    const float* Wq   = (const float*)d_in[1];
    const float* bq   = (const float*)d_in[2];
    const float* Wk   = (const float*)d_in[3];
    const float* bk   = (const float*)d_in[4];
    const float* Wv   = (const float*)d_in[5];
    const float* bv   = (const float*)d_in[6];
    const float* Wo   = (const float*)d_in[7];
    const float* bo   = (const float*)d_in[8];
    const float* W1   = (const float*)d_in[9];
    const float* b1   = (const float*)d_in[10];
    const float* W2   = (const float*)d_in[11];
    const float* b2   = (const float*)d_in[12];
    const float* gin  = (const float*)d_in[13];
    const float* bin  = (const float*)d_in[14];
    const float* gat  = (const float*)d_in[15];
    const float* bat  = (const float*)d_in[16];
    const float* gou  = (const float*)d_in[17];
    const float* bou  = (const float*)d_in[18];
    float* out = (float*)d_out;

    cudaFuncSetAttribute(mma_gemm<0>,
                         cudaFuncAttributeMaxDynamicSharedMemorySize, GSMEM);
    cudaFuncSetAttribute(mma_gemm<1>,
                         cudaFuncAttributeMaxDynamicSharedMemorySize, GSMEM);
    cudaFuncSetAttribute(flash_mma,
                         cudaFuncAttributeMaxDynamicSharedMemorySize, FLASH_SMEM);

    float *p_b0, *p_b1;
    __half *p_h, *p_qkv, *p_ao, *p_ff, *p_w;
    cudaGetSymbolAddress((void**)&p_b0,  g_buf0);
    cudaGetSymbolAddress((void**)&p_b1,  g_buf1);
    cudaGetSymbolAddress((void**)&p_h,   g_h);
    cudaGetSymbolAddress((void**)&p_qkv, g_qkv);
    cudaGetSymbolAddress((void**)&p_ao,  g_ao);
    cudaGetSymbolAddress((void**)&p_ff,  g_ff);
    cudaGetSymbolAddress((void**)&p_w,   g_w);

    cudaMemcpyAsync(p_b0, x, (size_t)ROWS * DMODEL * sizeof(float),
                    cudaMemcpyDeviceToDevice);
    float* cur = p_b0;
    float* nxt = p_b1;

    const dim3 gQKV(QKVN / 128, ROWS / 128);   // 24 x 32
    const dim3 gD(DMODEL / 128, ROWS / 128);   // 8 x 32
    const dim3 gF(FF / 128, ROWS / 128);       // 32 x 32
    const dim3 gA(SEQ / 128, BH);              // 16 x 32
    const dim3 tD(DMODEL / 32, DMODEL / 32);
    const dim3 t1(FF / 32, DMODEL / 32);
    const dim3 t2(DMODEL / 32, FF / 32);

    for (int l = 0; l < LNUM; l++) {
        const float* wq = Wq + (size_t)l * DMODEL * DMODEL;
        const float* wk = Wk + (size_t)l * DMODEL * DMODEL;
        const float* wv = Wv + (size_t)l * DMODEL * DMODEL;
        const float* wo = Wo + (size_t)l * DMODEL * DMODEL;
        const float* w1 = W1 + (size_t)l * DMODEL * FF;
        const float* w2 = W2 + (size_t)l * FF * DMODEL;
        const float* vbq = bq + (size_t)l * DMODEL;
        const float* vbk = bk + (size_t)l * DMODEL;
        const float* vbv = bv + (size_t)l * DMODEL;
        const float* vbo = bo + (size_t)l * DMODEL;
        const float* vb1 = b1 + (size_t)l * FF;
        const float* vb2 = b2 + (size_t)l * DMODEL;

        // h = LN(out) -> fp16
        ln_h_kernel<<<ROWS, 256>>>(cur, gin, bin, p_h);

        // fused QKV projection
        castT_kernel<<<tD, 256>>>(wq, p_w, DMODEL, DMODEL);
        castT_kernel<<<tD, 256>>>(wk, p_w + (size_t)DMODEL * DMODEL, DMODEL, DMODEL);
        castT_kernel<<<tD, 256>>>(wv, p_w + 2 * (size_t)DMODEL * DMODEL, DMODEL, DMODEL);
        mma_gemm<1><<<gQKV, 256, GSMEM>>>(p_h, p_w, vbq, vbk, vbv, DMODEL,
                                          nullptr, nullptr, p_qkv,
                                          ROWS, QKVN, DMODEL, 0);

        // fused attention -> ao fp16
        flash_mma<<<gA, 256, FLASH_SMEM>>>(p_qkv, p_ao);

        // out = out + ao @ Wo + bo (fp32)
        castT_kernel<<<tD, 256>>>(wo, p_w, DMODEL, DMODEL);
        mma_gemm<0><<<gD, 256, GSMEM>>>(p_ao, p_w, vbo, vbo, vbo, DMODEL,
                                        cur, nxt, nullptr,
                                        ROWS, DMODEL, DMODEL, 0);
        { float* t = cur; cur = nxt; nxt = t; }

        // FFN
        ln_h_kernel<<<ROWS, 256>>>(cur, gat, bat, p_h);
        castT_kernel<<<t1, 256>>>(w1, p_w, DMODEL, FF);
        mma_gemm<1><<<gF, 256, GSMEM>>>(p_h, p_w, vb1, vb1, vb1, FF,
                                        nullptr, nullptr, p_ff,
                                        ROWS, FF, DMODEL, 1);
        castT_kernel<<<t2, 256>>>(w2, p_w, FF, DMODEL);
        mma_gemm<0><<<gD, 256, GSMEM>>>(p_ff, p_w, vb2, vb2, vb2, DMODEL,
                                        cur, nxt, nullptr,
                                        ROWS, DMODEL, FF, 0);
        { float* t = cur; cur = nxt; nxt = t; }
    }

    ln_kernel<<<ROWS, 256>>>(cur, gou, bou, out);
}